// round 14
// baseline (speedup 1.0000x reference)
#include <cuda_runtime.h>
#include <math.h>
#include <stdint.h>

#define LMAX 4096
__device__ __align__(16) float g_x    [64*LMAX];
__device__ __align__(16) float g_t1   [64*256*256];
__device__ __align__(16) float g_t2   [64*128*128];
__device__ __align__(16) float g_s0   [64*4096];
__device__ __align__(16) float g_s1   [64*1024];
__device__ __align__(16) float g_s2   [64*256];
__device__ __align__(16) float g_xz   [256*LMAX];
__device__ __align__(16) float g_x1   [128*LMAX];
__device__ __align__(16) float g_x2   [128*LMAX];
__device__ __align__(16) float g_dts  [4*4*LMAX];
__device__ __align__(16) float g_Bm   [4*16*LMAX];   // [k][n][L]
__device__ __align__(16) float g_Cm   [4*16*LMAX];   // [k][n][L]
__device__ __align__(16) float g_delta[4*128*LMAX];
__device__ __align__(16) float g_ys   [4*128*LMAX];  // spatial order
__device__ __align__(16) float g_yc   [128*LMAX];
__device__ __align__(16) float g_mu   [LMAX];
__device__ __align__(16) float g_rs   [LMAX];
__device__ __align__(16) uint32_t g_wtc[4*64*576];   // tf32 decoder weights

__device__ __forceinline__ float* bufptr(int id){
  switch(id){
    case 0: return g_x;
    case 2: return g_t1;
    case 3: return g_t2;
    case 4: return g_s0;
    case 5: return g_s1;
    default: return g_s2;
  }
}

__device__ __forceinline__ float siluf(float x){ return x / (1.0f + __expf(-x)); }
__device__ __forceinline__ float softplusf(float x){ return (x > 20.0f) ? x : log1pf(__expf(x)); }

__device__ __forceinline__ uint32_t f2tf(float v){
  uint32_t r; asm("cvt.rna.tf32.f32 %0, %1;" : "=r"(r) : "f"(v)); return r;
}
__device__ __forceinline__ void mma_tf32(float* d, uint32_t a0, uint32_t a1, uint32_t a2,
                                         uint32_t a3, uint32_t b0, uint32_t b1){
  asm("mma.sync.aligned.m16n8k8.row.col.f32.tf32.tf32.f32 "
      "{%0,%1,%2,%3},{%4,%5,%6,%7},{%8,%9},{%0,%1,%2,%3};"
      : "+f"(d[0]),"+f"(d[1]),"+f"(d[2]),"+f"(d[3])
      : "r"(a0),"r"(a1),"r"(a2),"r"(a3),"r"(b0),"r"(b1));
}

// ---------------- kernels ----------------

__global__ void k_patch_embed(const float* __restrict__ E0, const float* __restrict__ w,
                              const float* __restrict__ b){
  int idx = blockIdx.x*blockDim.x + threadIdx.x;
  if(idx >= 64*4096) return;
  int c = idx >> 12, p = idx & 4095;
  int oh = p >> 6, ow = p & 63;
  const float* wp = w + c*16;
  float acc = b[c];
  #pragma unroll
  for(int i=0;i<4;i++)
    #pragma unroll
    for(int j=0;j<4;j++)
      acc += E0[(oh*4+i)*256 + ow*4 + j] * wp[i*4+j];
  g_x[idx] = acc;
}

// precompute tf32 decoder weights: [0..2]=up_w convs, [3]=oc_w
__global__ void k_wprep(const float* __restrict__ upw, const float* __restrict__ ocw){
  int i = blockIdx.x*256 + threadIdx.x;
  if(i < 3*36864) g_wtc[i] = f2tf(upw[i]);
  else if(i < 4*36864) g_wtc[i] = f2tf(ocw[i - 3*36864]);
}

// warp-per-pixel LN over 64 channels (full normalize, for stage transitions)
__global__ void k_ln2d_w(int inid, int outid, const float* __restrict__ g,
                         const float* __restrict__ b, int L){
  int gid = (blockIdx.x*blockDim.x + threadIdx.x) >> 5;
  int lane = threadIdx.x & 31;
  if(gid >= L) return;
  const float* in = bufptr(inid);
  float* out = bufptr(outid);
  float v0 = in[lane*L + gid], v1 = in[(lane+32)*L + gid];
  float s = v0 + v1;
  #pragma unroll
  for(int o=16;o>0;o>>=1) s += __shfl_xor_sync(0xffffffffu, s, o);
  float mu = s*(1.0f/64.0f);
  float d0 = v0-mu, d1 = v1-mu;
  float q = d0*d0 + d1*d1;
  #pragma unroll
  for(int o=16;o>0;o>>=1) q += __shfl_xor_sync(0xffffffffu, q, o);
  float rs = rsqrtf(q*(1.0f/64.0f) + 1e-6f);
  out[lane*L + gid]      = d0*rs*g[lane]    + b[lane];
  out[(lane+32)*L + gid] = d1*rs*g[lane+32] + b[lane+32];
}

// coalesced thread-per-pixel LN stats (two-pass): writes g_mu/g_rs for g_x
__global__ void k_lnstats_v(int L){
  int p = blockIdx.x*256 + threadIdx.x;
  if(p >= L) return;
  float s = 0.f;
  #pragma unroll 1
  for(int c0=0;c0<64;c0+=16){
    float xr[16];
    #pragma unroll
    for(int j=0;j<16;j++) xr[j] = g_x[(c0+j)*L + p];
    #pragma unroll
    for(int j=0;j<16;j++) s += xr[j];
  }
  float mu = s*(1.0f/64.0f);
  float q = 0.f;
  #pragma unroll 1
  for(int c0=0;c0<64;c0+=16){
    float xr[16];
    #pragma unroll
    for(int j=0;j<16;j++) xr[j] = g_x[(c0+j)*L + p];
    #pragma unroll
    for(int j=0;j<16;j++){ float d = xr[j]-mu; q += d*d; }
  }
  g_mu[p] = mu;
  g_rs[p] = rsqrtf(q*(1.0f/64.0f) + 1e-6f);
}

// fused LN + in-proj (stats precomputed): 1 px/thread, 16 e per thread.
// Streaming channel batches of 16 -> low register pressure, high occupancy.
// grid(ceil(L/256), 16)
__global__ void __launch_bounds__(256) k_lninproj(const float* __restrict__ inw,
                        const float* __restrict__ lng, const float* __restrict__ lnb, int L){
  __shared__ __align__(16) float sw[64*16];
  __shared__ float sg[64], sb[64];
  int tid = threadIdx.x;
  int e0 = blockIdx.y*16;
  for(int i=tid;i<1024;i+=256) sw[i] = inw[(i>>4)*256 + e0 + (i&15)];
  if(tid < 64){ sg[tid]=lng[tid]; sb[tid]=lnb[tid]; }
  __syncthreads();
  int p = blockIdx.x*256 + tid;
  if(p >= L) return;
  float mu = g_mu[p], rs = g_rs[p];
  float acc[16];
  #pragma unroll
  for(int e=0;e<16;e++) acc[e]=0.f;
  #pragma unroll 1
  for(int c0=0;c0<64;c0+=16){
    float xr[16];
    #pragma unroll
    for(int j=0;j<16;j++) xr[j] = g_x[(c0+j)*L + p];
    #pragma unroll
    for(int j=0;j<16;j++){
      float h = (xr[j]-mu)*rs*sg[c0+j] + sb[c0+j];
      const float4* w4 = (const float4*)(sw + ((c0+j)<<4));
      #pragma unroll
      for(int q=0;q<4;q++){
        float4 v = w4[q];
        acc[4*q+0] += h*v.x; acc[4*q+1] += h*v.y;
        acc[4*q+2] += h*v.z; acc[4*q+3] += h*v.w;
      }
    }
  }
  #pragma unroll
  for(int e=0;e<16;e++)
    g_xz[(e0+e)*L + p] = acc[e];
}

// tiled depthwise 3x3 + silu; coalesced writes for BOTH orientations.
// grid(W/32, H/8, 128), block 256.
__global__ void k_dwconv_t(const float* __restrict__ w, const float* __restrict__ b,
                           int H, int W){
  __shared__ float sin_[10*34];
  __shared__ float sout[8*33];
  int L = H*W;
  int tid = threadIdx.x;
  int d = blockIdx.z;
  int x0 = blockIdx.x*32, y0 = blockIdx.y*8;
  const float* in = g_xz + d*L;
  for(int i=tid;i<340;i+=256){
    int rr = i/34, cc = i%34;
    int gy = y0-1+rr, gx = x0-1+cc;
    sin_[rr*34+cc] = (gy>=0 && gy<H && gx>=0 && gx<W) ? in[gy*W+gx] : 0.f;
  }
  float wr[9];
  #pragma unroll
  for(int kk=0;kk<9;kk++) wr[kk] = w[d*9+kk];
  __syncthreads();
  int r = tid >> 5, q = tid & 31;
  float acc = b[d];
  #pragma unroll
  for(int di=0;di<3;di++)
    #pragma unroll
    for(int dj=0;dj<3;dj++)
      acc += sin_[(r+di)*34 + q+dj]*wr[di*3+dj];
  float v = siluf(acc);
  g_x1[d*L + (y0+r)*W + x0+q] = v;
  sout[r*33+q] = v;
  __syncthreads();
  int ww = tid >> 3, hr = tid & 7;
  g_x2[d*L + (x0+ww)*H + (y0+hr)] = sout[hr*33+ww];
}

// fallback dwconv for small maps
__global__ void k_dwconv_tr(const float* __restrict__ w, const float* __restrict__ b,
                            int H, int W){
  int L = H*W;
  int idx = blockIdx.x*blockDim.x + threadIdx.x;
  if(idx >= 128*L) return;
  int d = idx / L, p = idx % L;
  int hh = p / W, ww = p % W;
  const float* in = g_xz + d*L;
  const float* wp = w + d*9;
  float acc = b[d];
  #pragma unroll
  for(int i=-1;i<=1;i++){
    int ih = hh+i; if(ih<0 || ih>=H) continue;
    #pragma unroll
    for(int j=-1;j<=1;j++){
      int iw = ww+j; if(iw<0 || iw>=W) continue;
      acc += in[ih*W+iw]*wp[(i+1)*3+(j+1)];
    }
  }
  float v = siluf(acc);
  g_x1[idx] = v;
  g_x2[d*L + ww*H + hh] = v;
}

// x-proj: 1 l/thread, 12 r per thread. grid(ceil(L/256), 4, 3)
__global__ void __launch_bounds__(256) k_xproj_v(const float* __restrict__ xpw, int L){
  __shared__ __align__(16) float sw[128*12];
  int tid = threadIdx.x;
  int k = blockIdx.y, rg = blockIdx.z;
  for(int i=tid;i<1536;i+=256){
    int d = i/12, j = i%12;
    sw[i] = xpw[k*4608 + (rg*12+j)*128 + d];
  }
  __syncthreads();
  int l = blockIdx.x*256 + tid;
  if(l >= L) return;
  int gl = (k >= 2) ? (L-1-l) : l;
  const float* base = ((k & 1) ? g_x2 : g_x1) + gl;
  float acc[12];
  #pragma unroll
  for(int j=0;j<12;j++) acc[j]=0.f;
  #pragma unroll 1
  for(int c0=0;c0<128;c0+=16){
    float xr[16];
    #pragma unroll
    for(int j=0;j<16;j++) xr[j] = base[(c0+j)*L];
    #pragma unroll
    for(int j=0;j<16;j++){
      const float4* w4 = (const float4*)(sw + (c0+j)*12);
      float4 a = w4[0], b2 = w4[1], c2 = w4[2];
      acc[0]+=xr[j]*a.x;  acc[1]+=xr[j]*a.y;  acc[2] +=xr[j]*a.z;  acc[3] +=xr[j]*a.w;
      acc[4]+=xr[j]*b2.x; acc[5]+=xr[j]*b2.y; acc[6] +=xr[j]*b2.z; acc[7] +=xr[j]*b2.w;
      acc[8]+=xr[j]*c2.x; acc[9]+=xr[j]*c2.y; acc[10]+=xr[j]*c2.z; acc[11]+=xr[j]*c2.w;
    }
  }
  #pragma unroll
  for(int j=0;j<12;j++){
    int r = rg*12 + j;
    float v = acc[j];
    if(r < 4)       g_dts[(k*4+r)*L + l] = v;
    else if(r < 20) g_Bm[(k*16 + (r-4))*L + l] = v;
    else            g_Cm[(k*16 + (r-20))*L + l] = v;
  }
}

// delta: grid(ceil(L/256), 512); blockIdx.y = kd
__global__ void k_delta_v(const float* __restrict__ dtw, const float* __restrict__ dtb, int L){
  int kd = blockIdx.y;
  int k = kd >> 7;
  int l = blockIdx.x*256 + threadIdx.x;
  if(l >= L) return;
  float4 w = *(const float4*)(dtw + kd*4);
  float a = dtb[kd]
          + g_dts[(k*4+0)*L + l]*w.x + g_dts[(k*4+1)*L + l]*w.y
          + g_dts[(k*4+2)*L + l]*w.z + g_dts[(k*4+3)*L + l]*w.w;
  g_delta[kd*L + l] = softplusf(a);
}

// fused 3-pass scan: 512 thr = 32 chunks x 16 n, 2 d per THREAD. grid(64, 4).
__global__ void k_scan(const float* __restrict__ alog, int L, int H, int W){
  __shared__ float s_aP[1024], s_hE[1024], s_hI[1024];
  int tid = threadIdx.x;
  int k = blockIdx.y;
  int d0 = blockIdx.x*2, d1 = d0+1;
  int c = tid >> 4, n = tid & 15;
  int CH = L >> 5;
  float A0 = -__expf(alog[(k*128+d0)*16+n]);
  float A1 = -__expf(alog[(k*128+d1)*16+n]);
  const float* __restrict__ dl0 = g_delta + (k*128+d0)*L;
  const float* __restrict__ dl1 = g_delta + (k*128+d1)*L;
  const float* upb = (k & 1) ? g_x2 : g_x1;
  const float* __restrict__ up0 = upb + d0*L;
  const float* __restrict__ up1 = upb + d1*L;
  bool rev = (k >= 2);
  const float* __restrict__ Bp = g_Bm + (k*16+n)*L;
  const float* __restrict__ Cp = g_Cm + (k*16+n)*L;
  int l0 = c*CH;
  float h0=0.f, h1=0.f, sd0=0.f, sd1=0.f;

  if(CH >= 4){
    for(int l=l0; l<l0+CH; l+=4){
      float4 B4 = *(const float4*)(Bp+l);
      float4 D0 = *(const float4*)(dl0+l);
      float4 D1 = *(const float4*)(dl1+l);
      float4 U0, U1;
      if(!rev){ U0 = *(const float4*)(up0+l); U1 = *(const float4*)(up1+l); }
      else{
        float4 t0 = *(const float4*)(up0 + (L-4-l));
        float4 t1 = *(const float4*)(up1 + (L-4-l));
        U0 = make_float4(t0.w,t0.z,t0.y,t0.x);
        U1 = make_float4(t1.w,t1.z,t1.y,t1.x);
      }
      h0 = __expf(D0.x*A0)*h0 + D0.x*B4.x*U0.x;  h1 = __expf(D1.x*A1)*h1 + D1.x*B4.x*U1.x;
      sd0 += D0.x; sd1 += D1.x;
      h0 = __expf(D0.y*A0)*h0 + D0.y*B4.y*U0.y;  h1 = __expf(D1.y*A1)*h1 + D1.y*B4.y*U1.y;
      sd0 += D0.y; sd1 += D1.y;
      h0 = __expf(D0.z*A0)*h0 + D0.z*B4.z*U0.z;  h1 = __expf(D1.z*A1)*h1 + D1.z*B4.z*U1.z;
      sd0 += D0.z; sd1 += D1.z;
      h0 = __expf(D0.w*A0)*h0 + D0.w*B4.w*U0.w;  h1 = __expf(D1.w*A1)*h1 + D1.w*B4.w*U1.w;
      sd0 += D0.w; sd1 += D1.w;
    }
  } else {
    for(int l=l0; l<l0+CH; l++){
      int gl = rev ? (L-1-l) : l;
      float Bv = Bp[l];
      float dlt0 = dl0[l], dlt1 = dl1[l];
      float uv0 = up0[gl], uv1 = up1[gl];
      h0 = __expf(dlt0*A0)*h0 + dlt0*Bv*uv0;
      h1 = __expf(dlt1*A1)*h1 + dlt1*Bv*uv1;
      sd0 += dlt0; sd1 += dlt1;
    }
  }
  s_aP[tid]     = __expf(A0*sd0); s_hE[tid]     = h0;
  s_aP[512+tid] = __expf(A1*sd1); s_hE[512+tid] = h1;
  __syncthreads();
  if(tid < 32){
    int dg = tid >> 4, n2 = tid & 15;
    int base = dg*512 + n2;
    float hh = 0.f;
    #pragma unroll 4
    for(int c2=0;c2<32;c2++){
      int a = base + c2*16;
      s_hI[a] = hh;
      hh = s_aP[a]*hh + s_hE[a];
    }
  }
  __syncthreads();
  h0 = s_hI[tid]; h1 = s_hI[512+tid];
  float* __restrict__ ysp0 = g_ys + (k*128+d0)*L;
  float* __restrict__ ysp1 = g_ys + (k*128+d1)*L;

  if(CH >= 4){
    for(int l=l0; l<l0+CH; l+=4){
      float4 B4 = *(const float4*)(Bp+l);
      float4 C4 = *(const float4*)(Cp+l);
      float4 D0 = *(const float4*)(dl0+l);
      float4 D1 = *(const float4*)(dl1+l);
      float4 U0, U1;
      if(!rev){ U0 = *(const float4*)(up0+l); U1 = *(const float4*)(up1+l); }
      else{
        float4 t0 = *(const float4*)(up0 + (L-4-l));
        float4 t1 = *(const float4*)(up1 + (L-4-l));
        U0 = make_float4(t0.w,t0.z,t0.y,t0.x);
        U1 = make_float4(t1.w,t1.z,t1.y,t1.x);
      }
      float dv0[4] = {D0.x,D0.y,D0.z,D0.w};
      float dv1[4] = {D1.x,D1.y,D1.z,D1.w};
      float bv[4]  = {B4.x,B4.y,B4.z,B4.w};
      float cv[4]  = {C4.x,C4.y,C4.z,C4.w};
      float u0[4]  = {U0.x,U0.y,U0.z,U0.w};
      float u1[4]  = {U1.x,U1.y,U1.z,U1.w};
      #pragma unroll
      for(int j=0;j<4;j++){
        h0 = __expf(dv0[j]*A0)*h0 + dv0[j]*bv[j]*u0[j];
        h1 = __expf(dv1[j]*A1)*h1 + dv1[j]*bv[j]*u1[j];
        float pr0 = h0*cv[j], pr1 = h1*cv[j];
        pr0 += __shfl_xor_sync(0xffffffffu, pr0, 8);
        pr1 += __shfl_xor_sync(0xffffffffu, pr1, 8);
        pr0 += __shfl_xor_sync(0xffffffffu, pr0, 4);
        pr1 += __shfl_xor_sync(0xffffffffu, pr1, 4);
        pr0 += __shfl_xor_sync(0xffffffffu, pr0, 2);
        pr1 += __shfl_xor_sync(0xffffffffu, pr1, 2);
        pr0 += __shfl_xor_sync(0xffffffffu, pr0, 1);
        pr1 += __shfl_xor_sync(0xffffffffu, pr1, 1);
        if(n == 0){
          int ll = l + j;
          int pos;
          if(k == 0) pos = ll;
          else if(k == 1) pos = (ll % H)*W + ll/H;
          else if(k == 2) pos = L-1-ll;
          else { int m = L-1-ll; pos = (m % H)*W + m/H; }
          ysp0[pos] = pr0;
          ysp1[pos] = pr1;
        }
      }
    }
  } else {
    for(int l=l0; l<l0+CH; l++){
      int gl = rev ? (L-1-l) : l;
      float Bv = Bp[l], Cv = Cp[l];
      float dlt0 = dl0[l], dlt1 = dl1[l];
      float uv0 = up0[gl], uv1 = up1[gl];
      h0 = __expf(dlt0*A0)*h0 + dlt0*Bv*uv0;
      h1 = __expf(dlt1*A1)*h1 + dlt1*Bv*uv1;
      float pr0 = h0*Cv, pr1 = h1*Cv;
      pr0 += __shfl_xor_sync(0xffffffffu, pr0, 8);
      pr1 += __shfl_xor_sync(0xffffffffu, pr1, 8);
      pr0 += __shfl_xor_sync(0xffffffffu, pr0, 4);
      pr1 += __shfl_xor_sync(0xffffffffu, pr1, 4);
      pr0 += __shfl_xor_sync(0xffffffffu, pr0, 2);
      pr1 += __shfl_xor_sync(0xffffffffu, pr1, 2);
      pr0 += __shfl_xor_sync(0xffffffffu, pr0, 1);
      pr1 += __shfl_xor_sync(0xffffffffu, pr1, 1);
      if(n == 0){
        int pos;
        if(k == 0) pos = l;
        else if(k == 1) pos = (l % H)*W + l/H;
        else if(k == 2) pos = L-1-l;
        else { int m = L-1-l; pos = (m % H)*W + m/H; }
        ysp0[pos] = pr0;
        ysp1[pos] = pr1;
      }
    }
  }
}

// fused combine + out-LN + *silu(z). grid(L/32), block 256
__global__ void k_post(const float* __restrict__ Dpw, const float* __restrict__ og,
                       const float* __restrict__ ob, int L){
  __shared__ float sds[128], sog[128], sob[128];
  __shared__ float red[8*32];
  __shared__ float smu[32], srs[32];
  int tid = threadIdx.x;
  if(tid < 128){
    sds[tid] = Dpw[tid] + Dpw[128+tid] + Dpw[256+tid] + Dpw[384+tid];
    sog[tid] = og[tid]; sob[tid] = ob[tid];
  }
  __syncthreads();
  int p = tid & 31, dg = tid >> 5;
  int pp = blockIdx.x*32 + p;
  float v[16];
  float s = 0.f;
  #pragma unroll
  for(int dd=0;dd<16;dd++){
    int d = dg*16 + dd;
    float a = g_ys[d*L + pp] + g_ys[(128+d)*L + pp]
            + g_ys[(256+d)*L + pp] + g_ys[(384+d)*L + pp]
            + sds[d]*g_x1[d*L + pp];
    v[dd] = a; s += a;
  }
  red[dg*32+p] = s;
  __syncthreads();
  if(dg == 0){
    float a = 0.f;
    #pragma unroll
    for(int j=0;j<8;j++) a += red[j*32+p];
    smu[p] = a*(1.0f/128.0f);
  }
  __syncthreads();
  float mu = smu[p];
  float ss = 0.f;
  #pragma unroll
  for(int dd=0;dd<16;dd++){ float df = v[dd]-mu; ss += df*df; }
  red[dg*32+p] = ss;
  __syncthreads();
  if(dg == 0){
    float a = 0.f;
    #pragma unroll
    for(int j=0;j<8;j++) a += red[j*32+p];
    srs[p] = rsqrtf(a*(1.0f/128.0f) + 1e-6f);
  }
  __syncthreads();
  float rs = srs[p];
  #pragma unroll
  for(int dd=0;dd<16;dd++){
    int d = dg*16 + dd;
    float z = g_xz[(128+d)*L + pp];
    g_yc[d*L + pp] = ((v[dd]-mu)*rs*sog[d] + sob[d]) * siluf(z);
  }
}

// out-proj: 1 px/thread, 8 couts. grid(ceil(L/256), 8)
__global__ void k_outproj_v(const float* __restrict__ opw, int L, int skipid){
  __shared__ __align__(16) float sw[128*8];
  int tid = threadIdx.x;
  int c0 = blockIdx.y*8;
  for(int i=tid;i<1024;i+=256)
    sw[i] = opw[(i>>3)*64 + c0 + (i&7)];
  __syncthreads();
  int p = blockIdx.x*256 + tid;
  if(p >= L) return;
  float acc[8];
  #pragma unroll
  for(int c=0;c<8;c++) acc[c]=0.f;
  #pragma unroll 1
  for(int d0=0;d0<128;d0+=16){
    float yr[16];
    #pragma unroll
    for(int j=0;j<16;j++) yr[j] = g_yc[(d0+j)*L + p];
    #pragma unroll
    for(int j=0;j<16;j++){
      const float4* w4 = (const float4*)(sw + ((d0+j)<<3));
      float4 a = w4[0], b2 = w4[1];
      acc[0]+=yr[j]*a.x;  acc[1]+=yr[j]*a.y;  acc[2]+=yr[j]*a.z;  acc[3]+=yr[j]*a.w;
      acc[4]+=yr[j]*b2.x; acc[5]+=yr[j]*b2.y; acc[6]+=yr[j]*b2.z; acc[7]+=yr[j]*b2.w;
    }
  }
  float* skp = (skipid >= 0) ? bufptr(skipid) : nullptr;
  #pragma unroll
  for(int c=0;c<8;c++){
    int o = (c0+c)*L + p;
    float r = g_x[o] + acc[c];
    g_x[o] = r;
    if(skp) skp[o] = r;
  }
}

// tiled stride-2 conv: out tile 16co x 8h x 16w
__global__ void k_conv3x3_s2(int inid, const float* __restrict__ w, const float* __restrict__ b,
                             int outid, int Hi, int Wi, int Ho, int Wo){
  __shared__ float sin_[17*35];
  __shared__ float sw_[16*9];
  const float* in = bufptr(inid);
  float* out = bufptr(outid);
  int tid = threadIdx.x;
  int cog = tid >> 6;
  int r = (tid >> 3) & 7;
  int q = tid & 7;
  int ox0 = blockIdx.x*16, oy0 = blockIdx.y*8;
  int cobase = blockIdx.z*16;
  float acc[4][2];
  #pragma unroll
  for(int i=0;i<4;i++){ acc[i][0]=0.f; acc[i][1]=0.f; }

  for(int ci=0;ci<64;ci++){
    __syncthreads();
    const float* ip = in + ci*Hi*Wi;
    for(int i=tid;i<561;i+=256){
      int rr = i/33, cc = i%33;
      int gy = oy0*2 - 1 + rr, gx = ox0*2 - 1 + cc;
      sin_[rr*35+cc] = (gy>=0 && gy<Hi && gx>=0 && gx<Wi) ? ip[gy*Wi+gx] : 0.f;
    }
    for(int i=tid;i<144;i+=256)
      sw_[i] = w[(cobase + i/9)*576 + ci*9 + i%9];
    __syncthreads();
    float inr[3][5];
    #pragma unroll
    for(int di=0;di<3;di++)
      #pragma unroll
      for(int dj=0;dj<5;dj++)
        inr[di][dj] = sin_[(2*r+di)*35 + 4*q + dj];
    #pragma unroll
    for(int co=0;co<4;co++){
      float wr[9];
      #pragma unroll
      for(int kk=0;kk<9;kk++) wr[kk] = sw_[(cog*4+co)*9 + kk];
      #pragma unroll
      for(int px=0;px<2;px++){
        float sa = acc[co][px];
        #pragma unroll
        for(int di=0;di<3;di++)
          #pragma unroll
          for(int dj=0;dj<3;dj++)
            sa += wr[di*3+dj]*inr[di][dj+2*px];
        acc[co][px] = sa;
      }
    }
  }
  int oh = oy0 + r;
  #pragma unroll
  for(int co=0;co<4;co++){
    int c = cobase + cog*4 + co;
    float bb = b[c];
    #pragma unroll
    for(int px=0;px<2;px++){
      int ow = ox0 + 2*q + px;
      if(oh < Ho && ow < Wo)
        out[c*Ho*Wo + oh*Wo + ow] = acc[co][px] + bb;
    }
  }
}

// scalar tiled conv with fused bilinear resize (fallback for small maps).
__global__ void __launch_bounds__(256) k_conv3x3_rt(int inid, const float* __restrict__ w,
                             const float* __restrict__ b,
                             int skipid, int outid, float* __restrict__ extout,
                             int Hi, int Wi, int H, int W, int dosilu){
  __shared__ float sin_[10*35];
  __shared__ float sw_[16*9];
  __shared__ int   sy0[10], sy1[10], syok[10];
  __shared__ float swy[10];
  __shared__ int   sx0[34], sx1[34], sxok[34];
  __shared__ float swx[34];
  const float* in = bufptr(inid);
  float* out = (outid < 0) ? extout : bufptr(outid);
  int tid = threadIdx.x;
  int qid = tid & 63;
  int cog = tid >> 6;
  int r   = qid >> 3;
  int q   = qid & 7;
  int ox0 = blockIdx.x*32, oy0 = blockIdx.y*8;
  int cobase = blockIdx.z*16;
  float scy = (float)Hi/(float)H, scx = (float)Wi/(float)W;

  if(tid < 10){
    int oy = oy0-1+tid;
    syok[tid] = (oy>=0 && oy<H) ? 1 : 0;
    float fy = (oy + 0.5f)*scy - 0.5f;
    int y0 = (int)floorf(fy);
    swy[tid] = fy - (float)y0;
    sy0[tid] = max(y0,0)*Wi;
    sy1[tid] = min(y0+1, Hi-1)*Wi;
  }
  if(tid >= 32 && tid < 66){
    int i = tid-32;
    int ox = ox0-1+i;
    sxok[i] = (ox>=0 && ox<W) ? 1 : 0;
    float fx = (ox + 0.5f)*scx - 0.5f;
    int x0 = (int)floorf(fx);
    swx[i] = fx - (float)x0;
    sx0[i] = max(x0,0);
    sx1[i] = min(x0+1, Wi-1);
  }

  float acc[4][4];
  #pragma unroll
  for(int i=0;i<4;i++)
    #pragma unroll
    for(int j=0;j<4;j++) acc[i][j]=0.f;

  for(int ci=0;ci<64;ci++){
    __syncthreads();
    const float* ip = in + ci*Hi*Wi;
    for(int i=tid;i<340;i+=256){
      int rr = i/34, cc = i%34;
      float v = 0.f;
      if(syok[rr] && sxok[cc]){
        float wy = swy[rr], wx = swx[cc];
        const float* r0 = ip + sy0[rr];
        const float* r1 = ip + sy1[rr];
        float a = r0[sx0[cc]], b2 = r0[sx1[cc]];
        float c2 = r1[sx0[cc]], d2 = r1[sx1[cc]];
        v = (1.f-wy)*((1.f-wx)*a + wx*b2) + wy*((1.f-wx)*c2 + wx*d2);
      }
      sin_[rr*35+cc] = v;
    }
    for(int i=tid;i<144;i+=256)
      sw_[i] = w[(cobase + i/9)*576 + ci*9 + i%9];
    __syncthreads();
    float inr[3][6];
    #pragma unroll
    for(int di=0;di<3;di++)
      #pragma unroll
      for(int dj=0;dj<6;dj++)
        inr[di][dj] = sin_[(r+di)*35 + 4*q + dj];
    #pragma unroll
    for(int co=0;co<4;co++){
      float wr[9];
      #pragma unroll
      for(int kk=0;kk<9;kk++) wr[kk] = sw_[(cog*4+co)*9 + kk];
      #pragma unroll
      for(int px=0;px<4;px++){
        float sacc = acc[co][px];
        #pragma unroll
        for(int di=0;di<3;di++)
          #pragma unroll
          for(int dj=0;dj<3;dj++)
            sacc += wr[di*3+dj]*inr[di][dj+px];
        acc[co][px] = sacc;
      }
    }
  }
  int gy = oy0 + r;
  #pragma unroll
  for(int co=0;co<4;co++){
    int c = cobase + cog*4 + co;
    float bb = b[c];
    #pragma unroll
    for(int px=0;px<4;px++){
      int gx = ox0 + 4*q + px;
      if(gy < H && gx < W){
        float v = acc[co][px] + bb;
        if(dosilu) v = siluf(v);
        int o = c*H*W + gy*W + gx;
        if(skipid >= 0) v += bufptr(skipid)[o];
        out[o] = v;
      }
    }
  }
}

// tf32 tensor-core conv3x3 + fused bilinear resize; pre-converted weights in g_wtc.
// Block 256 thr (8 warps). Output tile: 64 co x (2 rows x 32 cols). grid(W/32, H/2).
__global__ void __launch_bounds__(256) k_conv3x3_tc(int inid, int wbase,
                             const float* __restrict__ b,
                             int skipid, int outid, float* __restrict__ extout,
                             int Hi, int Wi, int H, int W, int dosilu){
  __shared__ __align__(16) uint32_t shal[8*136];
  __shared__ __align__(16) uint32_t swt[64*72];
  __shared__ int   sy0[4], sy1[4], syok[4];
  __shared__ float swy[4];
  __shared__ int   sx0[34], sx1[34], sxok[34];
  __shared__ float swx[34];
  const float* in = bufptr(inid);
  float* out = (outid < 0) ? extout : bufptr(outid);
  int tid = threadIdx.x;
  int lane = tid & 31, wid = tid >> 5;
  int mt = wid >> 1, nh = wid & 1;
  int g = lane >> 2, r0 = lane & 3;
  int ox0 = blockIdx.x*32, oy0 = blockIdx.y*2;
  float scy = (float)Hi/(float)H, scx = (float)Wi/(float)W;

  if(tid < 4){
    int oy = oy0-1+tid;
    syok[tid] = (oy>=0 && oy<H) ? 1 : 0;
    float fy = (oy + 0.5f)*scy - 0.5f;
    int y0 = (int)floorf(fy);
    swy[tid] = fy - (float)y0;
    sy0[tid] = max(y0,0)*Wi;
    sy1[tid] = min(y0+1, Hi-1)*Wi;
  }
  if(tid >= 32 && tid < 66){
    int i = tid-32;
    int ox = ox0-1+i;
    sxok[i] = (ox>=0 && ox<W) ? 1 : 0;
    float fx = (ox + 0.5f)*scx - 0.5f;
    int x0 = (int)floorf(fx);
    swx[i] = fx - (float)x0;
    sx0[i] = max(x0,0);
    sx1[i] = min(x0+1, Wi-1);
  }

  float acc[4][4];
  #pragma unroll
  for(int i=0;i<4;i++)
    #pragma unroll
    for(int j=0;j<4;j++) acc[i][j]=0.f;

  for(int cig=0; cig<8; cig++){
    __syncthreads();
    for(int i=tid;i<1088;i+=256){
      int pl = i/136, pos = i%136;
      int rr = pos/34, cc = pos%34;
      float v = 0.f;
      if(syok[rr] && sxok[cc]){
        const float* ip = in + (cig*8+pl)*Hi*Wi;
        float wy = swy[rr], wx = swx[cc];
        const float* q0 = ip + sy0[rr];
        const float* q1 = ip + sy1[rr];
        float a = q0[sx0[cc]], b2 = q0[sx1[cc]];
        float c2 = q1[sx0[cc]], d2 = q1[sx1[cc]];
        v = (1.f-wy)*((1.f-wx)*a + wx*b2) + wy*((1.f-wx)*c2 + wx*d2);
      }
      shal[i] = f2tf(v);
    }
    for(int j=tid; j<1152; j+=256){
      int i = j*4;
      int co = i/72, rem = i%72;
      *((uint4*)(swt + i)) = *((const uint4*)(g_wtc + wbase + co*576 + cig*72 + rem));
    }
    __syncthreads();
    #pragma unroll
    for(int tp=0;tp<9;tp++){
      int dy = tp/3, dx = tp%3;
      uint32_t a0 = swt[(mt*16+g)*72   + r0*9     + tp];
      uint32_t a1 = swt[(mt*16+g+8)*72 + r0*9     + tp];
      uint32_t a2 = swt[(mt*16+g)*72   + (r0+4)*9 + tp];
      uint32_t a3 = swt[(mt*16+g+8)*72 + (r0+4)*9 + tp];
      #pragma unroll
      for(int nt=0;nt<4;nt++){
        int n = (nh*4+nt)*8 + g;
        int py = n >> 5, px = n & 31;
        int addr = (py+dy)*34 + px + dx;
        uint32_t b0 = shal[r0*136 + addr];
        uint32_t b1 = shal[(r0+4)*136 + addr];
        mma_tf32(acc[nt], a0, a1, a2, a3, b0, b1);
      }
    }
  }

  float bb0 = b[mt*16+g], bb1 = b[mt*16+g+8];
  float* skp = (skipid >= 0) ? bufptr(skipid) : nullptr;
  #pragma unroll
  for(int nt=0;nt<4;nt++){
    int n0 = (nh*4+nt)*8 + r0*2;
    int py = n0 >> 5, px = n0 & 31;
    int gy = oy0 + py, gx = ox0 + px;
    #pragma unroll
    for(int half=0; half<2; half++){
      int co = mt*16 + g + half*8;
      float v0 = acc[nt][half*2+0] + (half ? bb1 : bb0);
      float v1 = acc[nt][half*2+1] + (half ? bb1 : bb0);
      if(dosilu){ v0 = siluf(v0); v1 = siluf(v1); }
      int o = co*H*W + gy*W + gx;
      if(skp){ v0 += skp[o]; v1 += skp[o+1]; }
      out[o]   = v0;
      out[o+1] = v1;
    }
  }
}

// ---------------- host orchestration ----------------
static inline int gs(int n, int bs){ return (n + bs - 1)/bs; }

extern "C" void kernel_launch(void* const* d_in, const int* in_sizes, int n_in,
                              void* d_out, int out_size){
  const float* E0     = (const float*)d_in[0];
  const float* pe_w   = (const float*)d_in[1];
  const float* pe_b   = (const float*)d_in[2];
  const float* pe_lg  = (const float*)d_in[3];
  const float* pe_lb  = (const float*)d_in[4];
  const float* ln_g   = (const float*)d_in[5];
  const float* ln_b   = (const float*)d_in[6];
  const float* in_w   = (const float*)d_in[7];
  const float* cv_w   = (const float*)d_in[8];
  const float* cv_b   = (const float*)d_in[9];
  const float* xp_w   = (const float*)d_in[10];
  const float* dt_w   = (const float*)d_in[11];
  const float* dt_b   = (const float*)d_in[12];
  const float* A_log  = (const float*)d_in[13];
  const float* Dp     = (const float*)d_in[14];
  const float* on_g   = (const float*)d_in[15];
  const float* on_b   = (const float*)d_in[16];
  const float* out_pw = (const float*)d_in[17];
  const float* dn_w   = (const float*)d_in[18];
  const float* dn_b   = (const float*)d_in[19];
  const float* dn_g   = (const float*)d_in[20];
  const float* dn_lb  = (const float*)d_in[21];
  const float* up_w   = (const float*)d_in[22];
  const float* up_b   = (const float*)d_in[23];
  const float* oc_w   = (const float*)d_in[24];
  const float* oc_b   = (const float*)d_in[25];

  const int BS = 256;

  k_patch_embed<<<gs(64*4096,BS),BS>>>(E0, pe_w, pe_b);
  k_wprep<<<576,256>>>(up_w, oc_w);
  k_ln2d_w<<<gs(4096*32,BS),BS>>>(0, 0, pe_lg, pe_lb, 4096);

  auto vss = [&](int blk, int H, int skipid){
    int W = H, L = H*W;
    k_lnstats_v<<<gs(L,256),256>>>(L);
    k_lninproj <<<dim3(gs(L,256),16),256>>>(in_w + blk*64*256, ln_g + blk*64, ln_b + blk*64, L);
    if(W >= 32)
      k_dwconv_t<<<dim3(W/32, H/8, 128),256>>>(cv_w + blk*128*9, cv_b + blk*128, H, W);
    else
      k_dwconv_tr<<<gs(128*L,BS),BS>>>(cv_w + blk*128*9, cv_b + blk*128, H, W);
    k_xproj_v  <<<dim3(gs(L,256),4,3),256>>>(xp_w + blk*4*36*128, L);
    k_delta_v  <<<dim3(gs(L,256),512),256>>>(dt_w + blk*4*128*4, dt_b + blk*4*128, L);
    k_scan     <<<dim3(64,4),512>>>(A_log + blk*4*128*16, L, H, W);
    k_post     <<<L/32,256>>>(Dp + blk*4*128, on_g + blk*128, on_b + blk*128, L);
    k_outproj_v<<<dim3(gs(L,256),8),256>>>(out_pw + blk*128*64, L, skipid);
  };

  const int skipid[3] = {4, 5, 6};
  int H = 64;
  for(int st=0; st<4; st++){
    vss(st*2,   H, -1);
    vss(st*2+1, H, (st < 3) ? skipid[st] : -1);
    if(st < 3){
      int Ho = H/2;
      dim3 gdn(gs(Ho,16), gs(Ho,8), 4);
      k_conv3x3_s2<<<gdn,256>>>(0, dn_w + st*64*64*9, dn_b + st*64, 3, H, H, Ho, Ho);
      k_ln2d_w<<<gs(Ho*Ho*32,BS),BS>>>(3, 0, dn_g + st*64, dn_lb + st*64, Ho*Ho);
      H = Ho;
    }
  }

  int cur = 0;
  for(int i=0;i<3;i++){
    int Ho = H*2;
    int oth = (cur == 0) ? 2 : 0;
    if(Ho % 32 == 0){
      dim3 gconv(Ho/32, Ho/2);
      k_conv3x3_tc<<<gconv,256>>>(cur, i*36864, up_b + i*64,
                                  skipid[2-i], oth, nullptr, H, H, Ho, Ho, 1);
    } else {
      dim3 gconv(gs(Ho,32), gs(Ho,8), 4);
      k_conv3x3_rt<<<gconv,256>>>(cur, up_w + i*64*64*9, up_b + i*64,
                                  skipid[2-i], oth, nullptr, H, H, Ho, Ho, 1);
    }
    cur = oth;
    H = Ho;
  }

  dim3 gfin(8, 128);
  k_conv3x3_tc<<<gfin,256>>>(cur, 3*36864, oc_b, -1, -1, (float*)d_out,
                             64, 64, 256, 256, 1);
}

// round 15
// speedup vs baseline: 1.0157x; 1.0157x over previous
#include <cuda_runtime.h>
#include <math.h>
#include <stdint.h>

#define LMAX 4096
__device__ __align__(16) float g_x    [64*LMAX];
__device__ __align__(16) float g_t1   [64*256*256];
__device__ __align__(16) float g_t2   [64*128*128];
__device__ __align__(16) float g_s0   [64*4096];
__device__ __align__(16) float g_s1   [64*1024];
__device__ __align__(16) float g_s2   [64*256];
__device__ __align__(16) float g_xz   [256*LMAX];
__device__ __align__(16) float g_x1   [128*LMAX];
__device__ __align__(16) float g_x2   [128*LMAX];
__device__ __align__(16) float g_dts  [4*4*LMAX];
__device__ __align__(16) float g_Bm   [4*16*LMAX];   // [k][n][L]
__device__ __align__(16) float g_Cm   [4*16*LMAX];   // [k][n][L]
__device__ __align__(16) float g_delta[4*128*LMAX];
__device__ __align__(16) float g_ys   [4*128*LMAX];  // spatial order
__device__ __align__(16) float g_yc   [128*LMAX];
__device__ __align__(16) uint32_t g_wtc[4*64*576];   // tf32 decoder weights

__device__ __forceinline__ float* bufptr(int id){
  switch(id){
    case 0: return g_x;
    case 2: return g_t1;
    case 3: return g_t2;
    case 4: return g_s0;
    case 5: return g_s1;
    default: return g_s2;
  }
}

__device__ __forceinline__ float siluf(float x){ return x / (1.0f + __expf(-x)); }
__device__ __forceinline__ float softplusf(float x){ return (x > 20.0f) ? x : log1pf(__expf(x)); }

__device__ __forceinline__ uint32_t f2tf(float v){
  uint32_t r; asm("cvt.rna.tf32.f32 %0, %1;" : "=r"(r) : "f"(v)); return r;
}
__device__ __forceinline__ void mma_tf32(float* d, uint32_t a0, uint32_t a1, uint32_t a2,
                                         uint32_t a3, uint32_t b0, uint32_t b1){
  asm("mma.sync.aligned.m16n8k8.row.col.f32.tf32.tf32.f32 "
      "{%0,%1,%2,%3},{%4,%5,%6,%7},{%8,%9},{%0,%1,%2,%3};"
      : "+f"(d[0]),"+f"(d[1]),"+f"(d[2]),"+f"(d[3])
      : "r"(a0),"r"(a1),"r"(a2),"r"(a3),"r"(b0),"r"(b1));
}

// ---------------- kernels ----------------

__global__ void k_patch_embed(const float* __restrict__ E0, const float* __restrict__ w,
                              const float* __restrict__ b){
  int idx = blockIdx.x*blockDim.x + threadIdx.x;
  if(idx >= 64*4096) return;
  int c = idx >> 12, p = idx & 4095;
  int oh = p >> 6, ow = p & 63;
  const float* wp = w + c*16;
  float acc = b[c];
  #pragma unroll
  for(int i=0;i<4;i++)
    #pragma unroll
    for(int j=0;j<4;j++)
      acc += E0[(oh*4+i)*256 + ow*4 + j] * wp[i*4+j];
  g_x[idx] = acc;
}

// precompute tf32 decoder weights: [0..2]=up_w convs, [3]=oc_w
__global__ void k_wprep(const float* __restrict__ upw, const float* __restrict__ ocw){
  int i = blockIdx.x*256 + threadIdx.x;
  if(i < 3*36864) g_wtc[i] = f2tf(upw[i]);
  else if(i < 4*36864) g_wtc[i] = f2tf(ocw[i - 3*36864]);
}

// warp-per-pixel LN over 64 channels (full normalize, for stage transitions)
__global__ void k_ln2d_w(int inid, int outid, const float* __restrict__ g,
                         const float* __restrict__ b, int L){
  int gid = (blockIdx.x*blockDim.x + threadIdx.x) >> 5;
  int lane = threadIdx.x & 31;
  if(gid >= L) return;
  const float* in = bufptr(inid);
  float* out = bufptr(outid);
  float v0 = in[lane*L + gid], v1 = in[(lane+32)*L + gid];
  float s = v0 + v1;
  #pragma unroll
  for(int o=16;o>0;o>>=1) s += __shfl_xor_sync(0xffffffffu, s, o);
  float mu = s*(1.0f/64.0f);
  float d0 = v0-mu, d1 = v1-mu;
  float q = d0*d0 + d1*d1;
  #pragma unroll
  for(int o=16;o>0;o>>=1) q += __shfl_xor_sync(0xffffffffu, q, o);
  float rs = rsqrtf(q*(1.0f/64.0f) + 1e-6f);
  out[lane*L + gid]      = d0*rs*g[lane]    + b[lane];
  out[(lane+32)*L + gid] = d1*rs*g[lane+32] + b[lane+32];
}

// fused LN + in-proj: 1 px/thread, 16 e per thread. Streaming 3-pass
// (mean, var, GEMM) in 16-channel batches -> low regs, no xr[64] array.
// grid(ceil(L/256), 16)
__global__ void __launch_bounds__(256) k_lninproj(const float* __restrict__ inw,
                        const float* __restrict__ lng, const float* __restrict__ lnb, int L){
  __shared__ __align__(16) float sw[64*16];
  __shared__ float sg[64], sb[64];
  int tid = threadIdx.x;
  int e0 = blockIdx.y*16;
  for(int i=tid;i<1024;i+=256) sw[i] = inw[(i>>4)*256 + e0 + (i&15)];
  if(tid < 64){ sg[tid]=lng[tid]; sb[tid]=lnb[tid]; }
  __syncthreads();
  int p = blockIdx.x*256 + tid;
  if(p >= L) return;
  // pass 1: mean
  float s = 0.f;
  #pragma unroll 1
  for(int c0=0;c0<64;c0+=16){
    float xr[16];
    #pragma unroll
    for(int j=0;j<16;j++) xr[j] = g_x[(c0+j)*L + p];
    #pragma unroll
    for(int j=0;j<16;j++) s += xr[j];
  }
  float mu = s*(1.0f/64.0f);
  // pass 2: variance
  float q = 0.f;
  #pragma unroll 1
  for(int c0=0;c0<64;c0+=16){
    float xr[16];
    #pragma unroll
    for(int j=0;j<16;j++) xr[j] = g_x[(c0+j)*L + p];
    #pragma unroll
    for(int j=0;j<16;j++){ float d = xr[j]-mu; q += d*d; }
  }
  float rs = rsqrtf(q*(1.0f/64.0f) + 1e-6f);
  // pass 3: normalize + GEMM
  float acc[16];
  #pragma unroll
  for(int e=0;e<16;e++) acc[e]=0.f;
  #pragma unroll 1
  for(int c0=0;c0<64;c0+=16){
    float xr[16];
    #pragma unroll
    for(int j=0;j<16;j++) xr[j] = g_x[(c0+j)*L + p];
    #pragma unroll
    for(int j=0;j<16;j++){
      float h = (xr[j]-mu)*rs*sg[c0+j] + sb[c0+j];
      const float4* w4 = (const float4*)(sw + ((c0+j)<<4));
      #pragma unroll
      for(int qq=0;qq<4;qq++){
        float4 v = w4[qq];
        acc[4*qq+0] += h*v.x; acc[4*qq+1] += h*v.y;
        acc[4*qq+2] += h*v.z; acc[4*qq+3] += h*v.w;
      }
    }
  }
  #pragma unroll
  for(int e=0;e<16;e++)
    g_xz[(e0+e)*L + p] = acc[e];
}

// tiled depthwise 3x3 + silu; coalesced writes for BOTH orientations.
// grid(W/32, H/8, 128), block 256.
__global__ void k_dwconv_t(const float* __restrict__ w, const float* __restrict__ b,
                           int H, int W){
  __shared__ float sin_[10*34];
  __shared__ float sout[8*33];
  int L = H*W;
  int tid = threadIdx.x;
  int d = blockIdx.z;
  int x0 = blockIdx.x*32, y0 = blockIdx.y*8;
  const float* in = g_xz + d*L;
  for(int i=tid;i<340;i+=256){
    int rr = i/34, cc = i%34;
    int gy = y0-1+rr, gx = x0-1+cc;
    sin_[rr*34+cc] = (gy>=0 && gy<H && gx>=0 && gx<W) ? in[gy*W+gx] : 0.f;
  }
  float wr[9];
  #pragma unroll
  for(int kk=0;kk<9;kk++) wr[kk] = w[d*9+kk];
  __syncthreads();
  int r = tid >> 5, q = tid & 31;
  float acc = b[d];
  #pragma unroll
  for(int di=0;di<3;di++)
    #pragma unroll
    for(int dj=0;dj<3;dj++)
      acc += sin_[(r+di)*34 + q+dj]*wr[di*3+dj];
  float v = siluf(acc);
  g_x1[d*L + (y0+r)*W + x0+q] = v;
  sout[r*33+q] = v;
  __syncthreads();
  int ww = tid >> 3, hr = tid & 7;
  g_x2[d*L + (x0+ww)*H + (y0+hr)] = sout[hr*33+ww];
}

// fallback dwconv for small maps
__global__ void k_dwconv_tr(const float* __restrict__ w, const float* __restrict__ b,
                            int H, int W){
  int L = H*W;
  int idx = blockIdx.x*blockDim.x + threadIdx.x;
  if(idx >= 128*L) return;
  int d = idx / L, p = idx % L;
  int hh = p / W, ww = p % W;
  const float* in = g_xz + d*L;
  const float* wp = w + d*9;
  float acc = b[d];
  #pragma unroll
  for(int i=-1;i<=1;i++){
    int ih = hh+i; if(ih<0 || ih>=H) continue;
    #pragma unroll
    for(int j=-1;j<=1;j++){
      int iw = ww+j; if(iw<0 || iw>=W) continue;
      acc += in[ih*W+iw]*wp[(i+1)*3+(j+1)];
    }
  }
  float v = siluf(acc);
  g_x1[idx] = v;
  g_x2[d*L + ww*H + hh] = v;
}

// x-proj: 1 l/thread, 12 r per thread. grid(ceil(L/256), 4, 3)
__global__ void __launch_bounds__(256) k_xproj_v(const float* __restrict__ xpw, int L){
  __shared__ __align__(16) float sw[128*12];
  int tid = threadIdx.x;
  int k = blockIdx.y, rg = blockIdx.z;
  for(int i=tid;i<1536;i+=256){
    int d = i/12, j = i%12;
    sw[i] = xpw[k*4608 + (rg*12+j)*128 + d];
  }
  __syncthreads();
  int l = blockIdx.x*256 + tid;
  if(l >= L) return;
  int gl = (k >= 2) ? (L-1-l) : l;
  const float* base = ((k & 1) ? g_x2 : g_x1) + gl;
  float acc[12];
  #pragma unroll
  for(int j=0;j<12;j++) acc[j]=0.f;
  #pragma unroll 1
  for(int c0=0;c0<128;c0+=16){
    float xr[16];
    #pragma unroll
    for(int j=0;j<16;j++) xr[j] = base[(c0+j)*L];
    #pragma unroll
    for(int j=0;j<16;j++){
      const float4* w4 = (const float4*)(sw + (c0+j)*12);
      float4 a = w4[0], b2 = w4[1], c2 = w4[2];
      acc[0]+=xr[j]*a.x;  acc[1]+=xr[j]*a.y;  acc[2] +=xr[j]*a.z;  acc[3] +=xr[j]*a.w;
      acc[4]+=xr[j]*b2.x; acc[5]+=xr[j]*b2.y; acc[6] +=xr[j]*b2.z; acc[7] +=xr[j]*b2.w;
      acc[8]+=xr[j]*c2.x; acc[9]+=xr[j]*c2.y; acc[10]+=xr[j]*c2.z; acc[11]+=xr[j]*c2.w;
    }
  }
  #pragma unroll
  for(int j=0;j<12;j++){
    int r = rg*12 + j;
    float v = acc[j];
    if(r < 4)       g_dts[(k*4+r)*L + l] = v;
    else if(r < 20) g_Bm[(k*16 + (r-4))*L + l] = v;
    else            g_Cm[(k*16 + (r-20))*L + l] = v;
  }
}

// delta: grid(ceil(L/256), 512); blockIdx.y = kd
__global__ void k_delta_v(const float* __restrict__ dtw, const float* __restrict__ dtb, int L){
  int kd = blockIdx.y;
  int k = kd >> 7;
  int l = blockIdx.x*256 + threadIdx.x;
  if(l >= L) return;
  float4 w = *(const float4*)(dtw + kd*4);
  float a = dtb[kd]
          + g_dts[(k*4+0)*L + l]*w.x + g_dts[(k*4+1)*L + l]*w.y
          + g_dts[(k*4+2)*L + l]*w.z + g_dts[(k*4+3)*L + l]*w.w;
  g_delta[kd*L + l] = softplusf(a);
}

// fused 3-pass scan: 512 thr = 32 chunks x 16 n, 2 d per THREAD. grid(64, 4).
__global__ void k_scan(const float* __restrict__ alog, int L, int H, int W){
  __shared__ float s_aP[1024], s_hE[1024], s_hI[1024];
  int tid = threadIdx.x;
  int k = blockIdx.y;
  int d0 = blockIdx.x*2, d1 = d0+1;
  int c = tid >> 4, n = tid & 15;
  int CH = L >> 5;
  float A0 = -__expf(alog[(k*128+d0)*16+n]);
  float A1 = -__expf(alog[(k*128+d1)*16+n]);
  const float* __restrict__ dl0 = g_delta + (k*128+d0)*L;
  const float* __restrict__ dl1 = g_delta + (k*128+d1)*L;
  const float* upb = (k & 1) ? g_x2 : g_x1;
  const float* __restrict__ up0 = upb + d0*L;
  const float* __restrict__ up1 = upb + d1*L;
  bool rev = (k >= 2);
  const float* __restrict__ Bp = g_Bm + (k*16+n)*L;
  const float* __restrict__ Cp = g_Cm + (k*16+n)*L;
  int l0 = c*CH;
  float h0=0.f, h1=0.f, sd0=0.f, sd1=0.f;

  if(CH >= 4){
    for(int l=l0; l<l0+CH; l+=4){
      float4 B4 = *(const float4*)(Bp+l);
      float4 D0 = *(const float4*)(dl0+l);
      float4 D1 = *(const float4*)(dl1+l);
      float4 U0, U1;
      if(!rev){ U0 = *(const float4*)(up0+l); U1 = *(const float4*)(up1+l); }
      else{
        float4 t0 = *(const float4*)(up0 + (L-4-l));
        float4 t1 = *(const float4*)(up1 + (L-4-l));
        U0 = make_float4(t0.w,t0.z,t0.y,t0.x);
        U1 = make_float4(t1.w,t1.z,t1.y,t1.x);
      }
      h0 = __expf(D0.x*A0)*h0 + D0.x*B4.x*U0.x;  h1 = __expf(D1.x*A1)*h1 + D1.x*B4.x*U1.x;
      sd0 += D0.x; sd1 += D1.x;
      h0 = __expf(D0.y*A0)*h0 + D0.y*B4.y*U0.y;  h1 = __expf(D1.y*A1)*h1 + D1.y*B4.y*U1.y;
      sd0 += D0.y; sd1 += D1.y;
      h0 = __expf(D0.z*A0)*h0 + D0.z*B4.z*U0.z;  h1 = __expf(D1.z*A1)*h1 + D1.z*B4.z*U1.z;
      sd0 += D0.z; sd1 += D1.z;
      h0 = __expf(D0.w*A0)*h0 + D0.w*B4.w*U0.w;  h1 = __expf(D1.w*A1)*h1 + D1.w*B4.w*U1.w;
      sd0 += D0.w; sd1 += D1.w;
    }
  } else {
    for(int l=l0; l<l0+CH; l++){
      int gl = rev ? (L-1-l) : l;
      float Bv = Bp[l];
      float dlt0 = dl0[l], dlt1 = dl1[l];
      float uv0 = up0[gl], uv1 = up1[gl];
      h0 = __expf(dlt0*A0)*h0 + dlt0*Bv*uv0;
      h1 = __expf(dlt1*A1)*h1 + dlt1*Bv*uv1;
      sd0 += dlt0; sd1 += dlt1;
    }
  }
  s_aP[tid]     = __expf(A0*sd0); s_hE[tid]     = h0;
  s_aP[512+tid] = __expf(A1*sd1); s_hE[512+tid] = h1;
  __syncthreads();
  if(tid < 32){
    int dg = tid >> 4, n2 = tid & 15;
    int base = dg*512 + n2;
    float hh = 0.f;
    #pragma unroll 4
    for(int c2=0;c2<32;c2++){
      int a = base + c2*16;
      s_hI[a] = hh;
      hh = s_aP[a]*hh + s_hE[a];
    }
  }
  __syncthreads();
  h0 = s_hI[tid]; h1 = s_hI[512+tid];
  float* __restrict__ ysp0 = g_ys + (k*128+d0)*L;
  float* __restrict__ ysp1 = g_ys + (k*128+d1)*L;

  if(CH >= 4){
    for(int l=l0; l<l0+CH; l+=4){
      float4 B4 = *(const float4*)(Bp+l);
      float4 C4 = *(const float4*)(Cp+l);
      float4 D0 = *(const float4*)(dl0+l);
      float4 D1 = *(const float4*)(dl1+l);
      float4 U0, U1;
      if(!rev){ U0 = *(const float4*)(up0+l); U1 = *(const float4*)(up1+l); }
      else{
        float4 t0 = *(const float4*)(up0 + (L-4-l));
        float4 t1 = *(const float4*)(up1 + (L-4-l));
        U0 = make_float4(t0.w,t0.z,t0.y,t0.x);
        U1 = make_float4(t1.w,t1.z,t1.y,t1.x);
      }
      float dv0[4] = {D0.x,D0.y,D0.z,D0.w};
      float dv1[4] = {D1.x,D1.y,D1.z,D1.w};
      float bv[4]  = {B4.x,B4.y,B4.z,B4.w};
      float cv[4]  = {C4.x,C4.y,C4.z,C4.w};
      float u0[4]  = {U0.x,U0.y,U0.z,U0.w};
      float u1[4]  = {U1.x,U1.y,U1.z,U1.w};
      #pragma unroll
      for(int j=0;j<4;j++){
        h0 = __expf(dv0[j]*A0)*h0 + dv0[j]*bv[j]*u0[j];
        h1 = __expf(dv1[j]*A1)*h1 + dv1[j]*bv[j]*u1[j];
        float pr0 = h0*cv[j], pr1 = h1*cv[j];
        pr0 += __shfl_xor_sync(0xffffffffu, pr0, 8);
        pr1 += __shfl_xor_sync(0xffffffffu, pr1, 8);
        pr0 += __shfl_xor_sync(0xffffffffu, pr0, 4);
        pr1 += __shfl_xor_sync(0xffffffffu, pr1, 4);
        pr0 += __shfl_xor_sync(0xffffffffu, pr0, 2);
        pr1 += __shfl_xor_sync(0xffffffffu, pr1, 2);
        pr0 += __shfl_xor_sync(0xffffffffu, pr0, 1);
        pr1 += __shfl_xor_sync(0xffffffffu, pr1, 1);
        if(n == 0){
          int ll = l + j;
          int pos;
          if(k == 0) pos = ll;
          else if(k == 1) pos = (ll % H)*W + ll/H;
          else if(k == 2) pos = L-1-ll;
          else { int m = L-1-ll; pos = (m % H)*W + m/H; }
          ysp0[pos] = pr0;
          ysp1[pos] = pr1;
        }
      }
    }
  } else {
    for(int l=l0; l<l0+CH; l++){
      int gl = rev ? (L-1-l) : l;
      float Bv = Bp[l], Cv = Cp[l];
      float dlt0 = dl0[l], dlt1 = dl1[l];
      float uv0 = up0[gl], uv1 = up1[gl];
      h0 = __expf(dlt0*A0)*h0 + dlt0*Bv*uv0;
      h1 = __expf(dlt1*A1)*h1 + dlt1*Bv*uv1;
      float pr0 = h0*Cv, pr1 = h1*Cv;
      pr0 += __shfl_xor_sync(0xffffffffu, pr0, 8);
      pr1 += __shfl_xor_sync(0xffffffffu, pr1, 8);
      pr0 += __shfl_xor_sync(0xffffffffu, pr0, 4);
      pr1 += __shfl_xor_sync(0xffffffffu, pr1, 4);
      pr0 += __shfl_xor_sync(0xffffffffu, pr0, 2);
      pr1 += __shfl_xor_sync(0xffffffffu, pr1, 2);
      pr0 += __shfl_xor_sync(0xffffffffu, pr0, 1);
      pr1 += __shfl_xor_sync(0xffffffffu, pr1, 1);
      if(n == 0){
        int pos;
        if(k == 0) pos = l;
        else if(k == 1) pos = (l % H)*W + l/H;
        else if(k == 2) pos = L-1-l;
        else { int m = L-1-l; pos = (m % H)*W + m/H; }
        ysp0[pos] = pr0;
        ysp1[pos] = pr1;
      }
    }
  }
}

// fused combine + out-LN + *silu(z). grid(L/32), block 256
__global__ void k_post(const float* __restrict__ Dpw, const float* __restrict__ og,
                       const float* __restrict__ ob, int L){
  __shared__ float sds[128], sog[128], sob[128];
  __shared__ float red[8*32];
  __shared__ float smu[32], srs[32];
  int tid = threadIdx.x;
  if(tid < 128){
    sds[tid] = Dpw[tid] + Dpw[128+tid] + Dpw[256+tid] + Dpw[384+tid];
    sog[tid] = og[tid]; sob[tid] = ob[tid];
  }
  __syncthreads();
  int p = tid & 31, dg = tid >> 5;
  int pp = blockIdx.x*32 + p;
  float v[16];
  float s = 0.f;
  #pragma unroll
  for(int dd=0;dd<16;dd++){
    int d = dg*16 + dd;
    float a = g_ys[d*L + pp] + g_ys[(128+d)*L + pp]
            + g_ys[(256+d)*L + pp] + g_ys[(384+d)*L + pp]
            + sds[d]*g_x1[d*L + pp];
    v[dd] = a; s += a;
  }
  red[dg*32+p] = s;
  __syncthreads();
  if(dg == 0){
    float a = 0.f;
    #pragma unroll
    for(int j=0;j<8;j++) a += red[j*32+p];
    smu[p] = a*(1.0f/128.0f);
  }
  __syncthreads();
  float mu = smu[p];
  float ss = 0.f;
  #pragma unroll
  for(int dd=0;dd<16;dd++){ float df = v[dd]-mu; ss += df*df; }
  red[dg*32+p] = ss;
  __syncthreads();
  if(dg == 0){
    float a = 0.f;
    #pragma unroll
    for(int j=0;j<8;j++) a += red[j*32+p];
    srs[p] = rsqrtf(a*(1.0f/128.0f) + 1e-6f);
  }
  __syncthreads();
  float rs = srs[p];
  #pragma unroll
  for(int dd=0;dd<16;dd++){
    int d = dg*16 + dd;
    float z = g_xz[(128+d)*L + pp];
    g_yc[d*L + pp] = ((v[dd]-mu)*rs*sog[d] + sob[d]) * siluf(z);
  }
}

// out-proj: 1 px/thread, 8 couts. grid(ceil(L/256), 8)
__global__ void k_outproj_v(const float* __restrict__ opw, int L, int skipid){
  __shared__ __align__(16) float sw[128*8];
  int tid = threadIdx.x;
  int c0 = blockIdx.y*8;
  for(int i=tid;i<1024;i+=256)
    sw[i] = opw[(i>>3)*64 + c0 + (i&7)];
  __syncthreads();
  int p = blockIdx.x*256 + tid;
  if(p >= L) return;
  float acc[8];
  #pragma unroll
  for(int c=0;c<8;c++) acc[c]=0.f;
  #pragma unroll 1
  for(int d0=0;d0<128;d0+=16){
    float yr[16];
    #pragma unroll
    for(int j=0;j<16;j++) yr[j] = g_yc[(d0+j)*L + p];
    #pragma unroll
    for(int j=0;j<16;j++){
      const float4* w4 = (const float4*)(sw + ((d0+j)<<3));
      float4 a = w4[0], b2 = w4[1];
      acc[0]+=yr[j]*a.x;  acc[1]+=yr[j]*a.y;  acc[2]+=yr[j]*a.z;  acc[3]+=yr[j]*a.w;
      acc[4]+=yr[j]*b2.x; acc[5]+=yr[j]*b2.y; acc[6]+=yr[j]*b2.z; acc[7]+=yr[j]*b2.w;
    }
  }
  float* skp = (skipid >= 0) ? bufptr(skipid) : nullptr;
  #pragma unroll
  for(int c=0;c<8;c++){
    int o = (c0+c)*L + p;
    float r = g_x[o] + acc[c];
    g_x[o] = r;
    if(skp) skp[o] = r;
  }
}

// tiled stride-2 conv: out tile 16co x 8h x 16w
__global__ void k_conv3x3_s2(int inid, const float* __restrict__ w, const float* __restrict__ b,
                             int outid, int Hi, int Wi, int Ho, int Wo){
  __shared__ float sin_[17*35];
  __shared__ float sw_[16*9];
  const float* in = bufptr(inid);
  float* out = bufptr(outid);
  int tid = threadIdx.x;
  int cog = tid >> 6;
  int r = (tid >> 3) & 7;
  int q = tid & 7;
  int ox0 = blockIdx.x*16, oy0 = blockIdx.y*8;
  int cobase = blockIdx.z*16;
  float acc[4][2];
  #pragma unroll
  for(int i=0;i<4;i++){ acc[i][0]=0.f; acc[i][1]=0.f; }

  for(int ci=0;ci<64;ci++){
    __syncthreads();
    const float* ip = in + ci*Hi*Wi;
    for(int i=tid;i<561;i+=256){
      int rr = i/33, cc = i%33;
      int gy = oy0*2 - 1 + rr, gx = ox0*2 - 1 + cc;
      sin_[rr*35+cc] = (gy>=0 && gy<Hi && gx>=0 && gx<Wi) ? ip[gy*Wi+gx] : 0.f;
    }
    for(int i=tid;i<144;i+=256)
      sw_[i] = w[(cobase + i/9)*576 + ci*9 + i%9];
    __syncthreads();
    float inr[3][5];
    #pragma unroll
    for(int di=0;di<3;di++)
      #pragma unroll
      for(int dj=0;dj<5;dj++)
        inr[di][dj] = sin_[(2*r+di)*35 + 4*q + dj];
    #pragma unroll
    for(int co=0;co<4;co++){
      float wr[9];
      #pragma unroll
      for(int kk=0;kk<9;kk++) wr[kk] = sw_[(cog*4+co)*9 + kk];
      #pragma unroll
      for(int px=0;px<2;px++){
        float sa = acc[co][px];
        #pragma unroll
        for(int di=0;di<3;di++)
          #pragma unroll
          for(int dj=0;dj<3;dj++)
            sa += wr[di*3+dj]*inr[di][dj+2*px];
        acc[co][px] = sa;
      }
    }
  }
  int oh = oy0 + r;
  #pragma unroll
  for(int co=0;co<4;co++){
    int c = cobase + cog*4 + co;
    float bb = b[c];
    #pragma unroll
    for(int px=0;px<2;px++){
      int ow = ox0 + 2*q + px;
      if(oh < Ho && ow < Wo)
        out[c*Ho*Wo + oh*Wo + ow] = acc[co][px] + bb;
    }
  }
}

// scalar tiled conv with fused bilinear resize (fallback for small maps).
__global__ void __launch_bounds__(256) k_conv3x3_rt(int inid, const float* __restrict__ w,
                             const float* __restrict__ b,
                             int skipid, int outid, float* __restrict__ extout,
                             int Hi, int Wi, int H, int W, int dosilu){
  __shared__ float sin_[10*35];
  __shared__ float sw_[16*9];
  __shared__ int   sy0[10], sy1[10], syok[10];
  __shared__ float swy[10];
  __shared__ int   sx0[34], sx1[34], sxok[34];
  __shared__ float swx[34];
  const float* in = bufptr(inid);
  float* out = (outid < 0) ? extout : bufptr(outid);
  int tid = threadIdx.x;
  int qid = tid & 63;
  int cog = tid >> 6;
  int r   = qid >> 3;
  int q   = qid & 7;
  int ox0 = blockIdx.x*32, oy0 = blockIdx.y*8;
  int cobase = blockIdx.z*16;
  float scy = (float)Hi/(float)H, scx = (float)Wi/(float)W;

  if(tid < 10){
    int oy = oy0-1+tid;
    syok[tid] = (oy>=0 && oy<H) ? 1 : 0;
    float fy = (oy + 0.5f)*scy - 0.5f;
    int y0 = (int)floorf(fy);
    swy[tid] = fy - (float)y0;
    sy0[tid] = max(y0,0)*Wi;
    sy1[tid] = min(y0+1, Hi-1)*Wi;
  }
  if(tid >= 32 && tid < 66){
    int i = tid-32;
    int ox = ox0-1+i;
    sxok[i] = (ox>=0 && ox<W) ? 1 : 0;
    float fx = (ox + 0.5f)*scx - 0.5f;
    int x0 = (int)floorf(fx);
    swx[i] = fx - (float)x0;
    sx0[i] = max(x0,0);
    sx1[i] = min(x0+1, Wi-1);
  }

  float acc[4][4];
  #pragma unroll
  for(int i=0;i<4;i++)
    #pragma unroll
    for(int j=0;j<4;j++) acc[i][j]=0.f;

  for(int ci=0;ci<64;ci++){
    __syncthreads();
    const float* ip = in + ci*Hi*Wi;
    for(int i=tid;i<340;i+=256){
      int rr = i/34, cc = i%34;
      float v = 0.f;
      if(syok[rr] && sxok[cc]){
        float wy = swy[rr], wx = swx[cc];
        const float* r0 = ip + sy0[rr];
        const float* r1 = ip + sy1[rr];
        float a = r0[sx0[cc]], b2 = r0[sx1[cc]];
        float c2 = r1[sx0[cc]], d2 = r1[sx1[cc]];
        v = (1.f-wy)*((1.f-wx)*a + wx*b2) + wy*((1.f-wx)*c2 + wx*d2);
      }
      sin_[rr*35+cc] = v;
    }
    for(int i=tid;i<144;i+=256)
      sw_[i] = w[(cobase + i/9)*576 + ci*9 + i%9];
    __syncthreads();
    float inr[3][6];
    #pragma unroll
    for(int di=0;di<3;di++)
      #pragma unroll
      for(int dj=0;dj<6;dj++)
        inr[di][dj] = sin_[(r+di)*35 + 4*q + dj];
    #pragma unroll
    for(int co=0;co<4;co++){
      float wr[9];
      #pragma unroll
      for(int kk=0;kk<9;kk++) wr[kk] = sw_[(cog*4+co)*9 + kk];
      #pragma unroll
      for(int px=0;px<4;px++){
        float sacc = acc[co][px];
        #pragma unroll
        for(int di=0;di<3;di++)
          #pragma unroll
          for(int dj=0;dj<3;dj++)
            sacc += wr[di*3+dj]*inr[di][dj+px];
        acc[co][px] = sacc;
      }
    }
  }
  int gy = oy0 + r;
  #pragma unroll
  for(int co=0;co<4;co++){
    int c = cobase + cog*4 + co;
    float bb = b[c];
    #pragma unroll
    for(int px=0;px<4;px++){
      int gx = ox0 + 4*q + px;
      if(gy < H && gx < W){
        float v = acc[co][px] + bb;
        if(dosilu) v = siluf(v);
        int o = c*H*W + gy*W + gx;
        if(skipid >= 0) v += bufptr(skipid)[o];
        out[o] = v;
      }
    }
  }
}

// tf32 tensor-core conv3x3 + fused bilinear resize; pre-converted weights in g_wtc.
// Block 256 thr (8 warps). Output tile: 64 co x (2 rows x 32 cols). grid(W/32, H/2).
__global__ void __launch_bounds__(256) k_conv3x3_tc(int inid, int wbase,
                             const float* __restrict__ b,
                             int skipid, int outid, float* __restrict__ extout,
                             int Hi, int Wi, int H, int W, int dosilu){
  __shared__ __align__(16) uint32_t shal[8*136];
  __shared__ __align__(16) uint32_t swt[64*72];
  __shared__ int   sy0[4], sy1[4], syok[4];
  __shared__ float swy[4];
  __shared__ int   sx0[34], sx1[34], sxok[34];
  __shared__ float swx[34];
  const float* in = bufptr(inid);
  float* out = (outid < 0) ? extout : bufptr(outid);
  int tid = threadIdx.x;
  int lane = tid & 31, wid = tid >> 5;
  int mt = wid >> 1, nh = wid & 1;
  int g = lane >> 2, r0 = lane & 3;
  int ox0 = blockIdx.x*32, oy0 = blockIdx.y*2;
  float scy = (float)Hi/(float)H, scx = (float)Wi/(float)W;

  if(tid < 4){
    int oy = oy0-1+tid;
    syok[tid] = (oy>=0 && oy<H) ? 1 : 0;
    float fy = (oy + 0.5f)*scy - 0.5f;
    int y0 = (int)floorf(fy);
    swy[tid] = fy - (float)y0;
    sy0[tid] = max(y0,0)*Wi;
    sy1[tid] = min(y0+1, Hi-1)*Wi;
  }
  if(tid >= 32 && tid < 66){
    int i = tid-32;
    int ox = ox0-1+i;
    sxok[i] = (ox>=0 && ox<W) ? 1 : 0;
    float fx = (ox + 0.5f)*scx - 0.5f;
    int x0 = (int)floorf(fx);
    swx[i] = fx - (float)x0;
    sx0[i] = max(x0,0);
    sx1[i] = min(x0+1, Wi-1);
  }

  float acc[4][4];
  #pragma unroll
  for(int i=0;i<4;i++)
    #pragma unroll
    for(int j=0;j<4;j++) acc[i][j]=0.f;

  for(int cig=0; cig<8; cig++){
    __syncthreads();
    for(int i=tid;i<1088;i+=256){
      int pl = i/136, pos = i%136;
      int rr = pos/34, cc = pos%34;
      float v = 0.f;
      if(syok[rr] && sxok[cc]){
        const float* ip = in + (cig*8+pl)*Hi*Wi;
        float wy = swy[rr], wx = swx[cc];
        const float* q0 = ip + sy0[rr];
        const float* q1 = ip + sy1[rr];
        float a = q0[sx0[cc]], b2 = q0[sx1[cc]];
        float c2 = q1[sx0[cc]], d2 = q1[sx1[cc]];
        v = (1.f-wy)*((1.f-wx)*a + wx*b2) + wy*((1.f-wx)*c2 + wx*d2);
      }
      shal[i] = f2tf(v);
    }
    for(int j=tid; j<1152; j+=256){
      int i = j*4;
      int co = i/72, rem = i%72;
      *((uint4*)(swt + i)) = *((const uint4*)(g_wtc + wbase + co*576 + cig*72 + rem));
    }
    __syncthreads();
    #pragma unroll
    for(int tp=0;tp<9;tp++){
      int dy = tp/3, dx = tp%3;
      uint32_t a0 = swt[(mt*16+g)*72   + r0*9     + tp];
      uint32_t a1 = swt[(mt*16+g+8)*72 + r0*9     + tp];
      uint32_t a2 = swt[(mt*16+g)*72   + (r0+4)*9 + tp];
      uint32_t a3 = swt[(mt*16+g+8)*72 + (r0+4)*9 + tp];
      #pragma unroll
      for(int nt=0;nt<4;nt++){
        int n = (nh*4+nt)*8 + g;
        int py = n >> 5, px = n & 31;
        int addr = (py+dy)*34 + px + dx;
        uint32_t b0 = shal[r0*136 + addr];
        uint32_t b1 = shal[(r0+4)*136 + addr];
        mma_tf32(acc[nt], a0, a1, a2, a3, b0, b1);
      }
    }
  }

  float bb0 = b[mt*16+g], bb1 = b[mt*16+g+8];
  float* skp = (skipid >= 0) ? bufptr(skipid) : nullptr;
  #pragma unroll
  for(int nt=0;nt<4;nt++){
    int n0 = (nh*4+nt)*8 + r0*2;
    int py = n0 >> 5, px = n0 & 31;
    int gy = oy0 + py, gx = ox0 + px;
    #pragma unroll
    for(int half=0; half<2; half++){
      int co = mt*16 + g + half*8;
      float v0 = acc[nt][half*2+0] + (half ? bb1 : bb0);
      float v1 = acc[nt][half*2+1] + (half ? bb1 : bb0);
      if(dosilu){ v0 = siluf(v0); v1 = siluf(v1); }
      int o = co*H*W + gy*W + gx;
      if(skp){ v0 += skp[o]; v1 += skp[o+1]; }
      out[o]   = v0;
      out[o+1] = v1;
    }
  }
}

// ---------------- host orchestration ----------------
static inline int gs(int n, int bs){ return (n + bs - 1)/bs; }

extern "C" void kernel_launch(void* const* d_in, const int* in_sizes, int n_in,
                              void* d_out, int out_size){
  const float* E0     = (const float*)d_in[0];
  const float* pe_w   = (const float*)d_in[1];
  const float* pe_b   = (const float*)d_in[2];
  const float* pe_lg  = (const float*)d_in[3];
  const float* pe_lb  = (const float*)d_in[4];
  const float* ln_g   = (const float*)d_in[5];
  const float* ln_b   = (const float*)d_in[6];
  const float* in_w   = (const float*)d_in[7];
  const float* cv_w   = (const float*)d_in[8];
  const float* cv_b   = (const float*)d_in[9];
  const float* xp_w   = (const float*)d_in[10];
  const float* dt_w   = (const float*)d_in[11];
  const float* dt_b   = (const float*)d_in[12];
  const float* A_log  = (const float*)d_in[13];
  const float* Dp     = (const float*)d_in[14];
  const float* on_g   = (const float*)d_in[15];
  const float* on_b   = (const float*)d_in[16];
  const float* out_pw = (const float*)d_in[17];
  const float* dn_w   = (const float*)d_in[18];
  const float* dn_b   = (const float*)d_in[19];
  const float* dn_g   = (const float*)d_in[20];
  const float* dn_lb  = (const float*)d_in[21];
  const float* up_w   = (const float*)d_in[22];
  const float* up_b   = (const float*)d_in[23];
  const float* oc_w   = (const float*)d_in[24];
  const float* oc_b   = (const float*)d_in[25];

  const int BS = 256;

  k_patch_embed<<<gs(64*4096,BS),BS>>>(E0, pe_w, pe_b);
  k_wprep<<<576,256>>>(up_w, oc_w);
  k_ln2d_w<<<gs(4096*32,BS),BS>>>(0, 0, pe_lg, pe_lb, 4096);

  auto vss = [&](int blk, int H, int skipid){
    int W = H, L = H*W;
    k_lninproj <<<dim3(gs(L,256),16),256>>>(in_w + blk*64*256, ln_g + blk*64, ln_b + blk*64, L);
    if(W >= 32)
      k_dwconv_t<<<dim3(W/32, H/8, 128),256>>>(cv_w + blk*128*9, cv_b + blk*128, H, W);
    else
      k_dwconv_tr<<<gs(128*L,BS),BS>>>(cv_w + blk*128*9, cv_b + blk*128, H, W);
    k_xproj_v  <<<dim3(gs(L,256),4,3),256>>>(xp_w + blk*4*36*128, L);
    k_delta_v  <<<dim3(gs(L,256),512),256>>>(dt_w + blk*4*128*4, dt_b + blk*4*128, L);
    k_scan     <<<dim3(64,4),512>>>(A_log + blk*4*128*16, L, H, W);
    k_post     <<<L/32,256>>>(Dp + blk*4*128, on_g + blk*128, on_b + blk*128, L);
    k_outproj_v<<<dim3(gs(L,256),8),256>>>(out_pw + blk*128*64, L, skipid);
  };

  const int skipid[3] = {4, 5, 6};
  int H = 64;
  for(int st=0; st<4; st++){
    vss(st*2,   H, -1);
    vss(st*2+1, H, (st < 3) ? skipid[st] : -1);
    if(st < 3){
      int Ho = H/2;
      dim3 gdn(gs(Ho,16), gs(Ho,8), 4);
      k_conv3x3_s2<<<gdn,256>>>(0, dn_w + st*64*64*9, dn_b + st*64, 3, H, H, Ho, Ho);
      k_ln2d_w<<<gs(Ho*Ho*32,BS),BS>>>(3, 0, dn_g + st*64, dn_lb + st*64, Ho*Ho);
      H = Ho;
    }
  }

  int cur = 0;
  for(int i=0;i<3;i++){
    int Ho = H*2;
    int oth = (cur == 0) ? 2 : 0;
    if(Ho % 32 == 0){
      dim3 gconv(Ho/32, Ho/2);
      k_conv3x3_tc<<<gconv,256>>>(cur, i*36864, up_b + i*64,
                                  skipid[2-i], oth, nullptr, H, H, Ho, Ho, 1);
    } else {
      dim3 gconv(gs(Ho,32), gs(Ho,8), 4);
      k_conv3x3_rt<<<gconv,256>>>(cur, up_w + i*64*64*9, up_b + i*64,
                                  skipid[2-i], oth, nullptr, H, H, Ho, Ho, 1);
    }
    cur = oth;
    H = Ho;
  }

  dim3 gfin(8, 128);
  k_conv3x3_tc<<<gfin,256>>>(cur, 3*36864, oc_b, -1, -1, (float*)d_out,
                             64, 64, 256, 256, 1);
}

// round 16
// speedup vs baseline: 1.1724x; 1.1543x over previous
#include <cuda_runtime.h>
#include <math.h>
#include <stdint.h>

#define LMAX 4096
__device__ __align__(16) float g_x    [64*LMAX];
__device__ __align__(16) float g_t1   [64*256*256];
__device__ __align__(16) float g_t2   [64*128*128];
__device__ __align__(16) float g_s0   [64*4096];
__device__ __align__(16) float g_s1   [64*1024];
__device__ __align__(16) float g_s2   [64*256];
__device__ __align__(16) float g_xz   [256*LMAX];
__device__ __align__(16) float g_x1   [128*LMAX];
__device__ __align__(16) float g_x2   [128*LMAX];
__device__ __align__(16) float g_dts  [4*4*LMAX];
__device__ __align__(16) float g_Bm   [4*16*LMAX];   // [k][n][L]
__device__ __align__(16) float g_Cm   [4*16*LMAX];   // [k][n][L]
__device__ __align__(16) float g_delta[4*128*LMAX];
__device__ __align__(16) float g_ys   [4*128*LMAX];  // spatial order
__device__ __align__(16) float g_yc   [128*LMAX];
__device__ __align__(16) uint32_t g_wtc[4*64*576];   // tf32 decoder weights

__device__ __forceinline__ float* bufptr(int id){
  switch(id){
    case 0: return g_x;
    case 2: return g_t1;
    case 3: return g_t2;
    case 4: return g_s0;
    case 5: return g_s1;
    default: return g_s2;
  }
}

__device__ __forceinline__ float siluf(float x){ return x / (1.0f + __expf(-x)); }
__device__ __forceinline__ float softplusf(float x){ return (x > 20.0f) ? x : log1pf(__expf(x)); }

__device__ __forceinline__ uint32_t f2tf(float v){
  uint32_t r; asm("cvt.rna.tf32.f32 %0, %1;" : "=r"(r) : "f"(v)); return r;
}
__device__ __forceinline__ void mma_tf32(float* d, uint32_t a0, uint32_t a1, uint32_t a2,
                                         uint32_t a3, uint32_t b0, uint32_t b1){
  asm("mma.sync.aligned.m16n8k8.row.col.f32.tf32.tf32.f32 "
      "{%0,%1,%2,%3},{%4,%5,%6,%7},{%8,%9},{%0,%1,%2,%3};"
      : "+f"(d[0]),"+f"(d[1]),"+f"(d[2]),"+f"(d[3])
      : "r"(a0),"r"(a1),"r"(a2),"r"(a3),"r"(b0),"r"(b1));
}

// ---------------- kernels ----------------

__global__ void k_patch_embed(const float* __restrict__ E0, const float* __restrict__ w,
                              const float* __restrict__ b){
  int idx = blockIdx.x*blockDim.x + threadIdx.x;
  if(idx >= 64*4096) return;
  int c = idx >> 12, p = idx & 4095;
  int oh = p >> 6, ow = p & 63;
  const float* wp = w + c*16;
  float acc = b[c];
  #pragma unroll
  for(int i=0;i<4;i++)
    #pragma unroll
    for(int j=0;j<4;j++)
      acc += E0[(oh*4+i)*256 + ow*4 + j] * wp[i*4+j];
  g_x[idx] = acc;
}

// precompute tf32 decoder weights: [0..2]=up_w convs, [3]=oc_w
__global__ void k_wprep(const float* __restrict__ upw, const float* __restrict__ ocw){
  int i = blockIdx.x*256 + threadIdx.x;
  if(i < 3*36864) g_wtc[i] = f2tf(upw[i]);
  else if(i < 4*36864) g_wtc[i] = f2tf(ocw[i - 3*36864]);
}

// warp-per-pixel LN over 64 channels (stage transitions)
__global__ void k_ln2d_w(int inid, int outid, const float* __restrict__ g,
                         const float* __restrict__ b, int L){
  int gid = (blockIdx.x*blockDim.x + threadIdx.x) >> 5;
  int lane = threadIdx.x & 31;
  if(gid >= L) return;
  const float* in = bufptr(inid);
  float* out = bufptr(outid);
  float v0 = in[lane*L + gid], v1 = in[(lane+32)*L + gid];
  float s = v0 + v1;
  #pragma unroll
  for(int o=16;o>0;o>>=1) s += __shfl_xor_sync(0xffffffffu, s, o);
  float mu = s*(1.0f/64.0f);
  float d0 = v0-mu, d1 = v1-mu;
  float q = d0*d0 + d1*d1;
  #pragma unroll
  for(int o=16;o>0;o>>=1) q += __shfl_xor_sync(0xffffffffu, q, o);
  float rs = rsqrtf(q*(1.0f/64.0f) + 1e-6f);
  out[lane*L + gid]      = d0*rs*g[lane]    + b[lane];
  out[(lane+32)*L + gid] = d1*rs*g[lane+32] + b[lane+32];
}

// fused LN + in-proj (R12 version): 1 px/thread, 16 e per thread. grid(ceil(L/256), 16)
__global__ void __launch_bounds__(256) k_lninproj(const float* __restrict__ inw,
                        const float* __restrict__ lng, const float* __restrict__ lnb, int L){
  __shared__ __align__(16) float sw[64*16];
  __shared__ float sg[64], sb[64];
  int tid = threadIdx.x;
  int e0 = blockIdx.y*16;
  for(int i=tid;i<1024;i+=256) sw[i] = inw[(i>>4)*256 + e0 + (i&15)];
  if(tid < 64){ sg[tid]=lng[tid]; sb[tid]=lnb[tid]; }
  __syncthreads();
  int p = blockIdx.x*256 + tid;
  if(p >= L) return;
  float xr[64];
  #pragma unroll
  for(int c=0;c<64;c++) xr[c] = g_x[c*L+p];
  float mu = 0.f;
  #pragma unroll
  for(int c=0;c<64;c++) mu += xr[c];
  mu *= (1.0f/64.0f);
  float var = 0.f;
  #pragma unroll
  for(int c=0;c<64;c++){ float d = xr[c]-mu; var += d*d; }
  float rs = rsqrtf(var*(1.0f/64.0f) + 1e-6f);
  float acc[16];
  #pragma unroll
  for(int e=0;e<16;e++) acc[e]=0.f;
  #pragma unroll
  for(int c=0;c<64;c++){
    float h = (xr[c]-mu)*rs*sg[c] + sb[c];
    const float4* w4 = (const float4*)(sw + (c<<4));
    #pragma unroll
    for(int j=0;j<4;j++){
      float4 v = w4[j];
      acc[4*j+0] += h*v.x; acc[4*j+1] += h*v.y;
      acc[4*j+2] += h*v.z; acc[4*j+3] += h*v.w;
    }
  }
  #pragma unroll
  for(int e=0;e<16;e++)
    g_xz[(e0+e)*L + p] = acc[e];
}

// tiled depthwise 3x3 + silu; coalesced writes for BOTH orientations.
// grid(W/32, H/8, 128), block 256.
__global__ void k_dwconv_t(const float* __restrict__ w, const float* __restrict__ b,
                           int H, int W){
  __shared__ float sin_[10*34];
  __shared__ float sout[8*33];
  int L = H*W;
  int tid = threadIdx.x;
  int d = blockIdx.z;
  int x0 = blockIdx.x*32, y0 = blockIdx.y*8;
  const float* in = g_xz + d*L;
  for(int i=tid;i<340;i+=256){
    int rr = i/34, cc = i%34;
    int gy = y0-1+rr, gx = x0-1+cc;
    sin_[rr*34+cc] = (gy>=0 && gy<H && gx>=0 && gx<W) ? in[gy*W+gx] : 0.f;
  }
  float wr[9];
  #pragma unroll
  for(int kk=0;kk<9;kk++) wr[kk] = w[d*9+kk];
  __syncthreads();
  int r = tid >> 5, q = tid & 31;
  float acc = b[d];
  #pragma unroll
  for(int di=0;di<3;di++)
    #pragma unroll
    for(int dj=0;dj<3;dj++)
      acc += sin_[(r+di)*34 + q+dj]*wr[di*3+dj];
  float v = siluf(acc);
  g_x1[d*L + (y0+r)*W + x0+q] = v;
  sout[r*33+q] = v;
  __syncthreads();
  int ww = tid >> 3, hr = tid & 7;
  g_x2[d*L + (x0+ww)*H + (y0+hr)] = sout[hr*33+ww];
}

// fallback dwconv for small maps
__global__ void k_dwconv_tr(const float* __restrict__ w, const float* __restrict__ b,
                            int H, int W){
  int L = H*W;
  int idx = blockIdx.x*blockDim.x + threadIdx.x;
  if(idx >= 128*L) return;
  int d = idx / L, p = idx % L;
  int hh = p / W, ww = p % W;
  const float* in = g_xz + d*L;
  const float* wp = w + d*9;
  float acc = b[d];
  #pragma unroll
  for(int i=-1;i<=1;i++){
    int ih = hh+i; if(ih<0 || ih>=H) continue;
    #pragma unroll
    for(int j=-1;j<=1;j++){
      int iw = ww+j; if(iw<0 || iw>=W) continue;
      acc += in[ih*W+iw]*wp[(i+1)*3+(j+1)];
    }
  }
  float v = siluf(acc);
  g_x1[idx] = v;
  g_x2[d*L + ww*H + hh] = v;
}

// x-proj: 1 l/thread, 12 r per thread. grid(ceil(L/256), 4, 3)
__global__ void __launch_bounds__(256) k_xproj_v(const float* __restrict__ xpw, int L){
  __shared__ __align__(16) float sw[128*12];
  int tid = threadIdx.x;
  int k = blockIdx.y, rg = blockIdx.z;
  for(int i=tid;i<1536;i+=256){
    int d = i/12, j = i%12;
    sw[i] = xpw[k*4608 + (rg*12+j)*128 + d];
  }
  __syncthreads();
  int l = blockIdx.x*256 + tid;
  if(l >= L) return;
  int gl = (k >= 2) ? (L-1-l) : l;
  const float* base = ((k & 1) ? g_x2 : g_x1) + gl;
  float acc[12];
  #pragma unroll
  for(int j=0;j<12;j++) acc[j]=0.f;
  #pragma unroll 1
  for(int c0=0;c0<128;c0+=16){
    float xr[16];
    #pragma unroll
    for(int j=0;j<16;j++) xr[j] = base[(c0+j)*L];
    #pragma unroll
    for(int j=0;j<16;j++){
      const float4* w4 = (const float4*)(sw + (c0+j)*12);
      float4 a = w4[0], b2 = w4[1], c2 = w4[2];
      acc[0]+=xr[j]*a.x;  acc[1]+=xr[j]*a.y;  acc[2] +=xr[j]*a.z;  acc[3] +=xr[j]*a.w;
      acc[4]+=xr[j]*b2.x; acc[5]+=xr[j]*b2.y; acc[6] +=xr[j]*b2.z; acc[7] +=xr[j]*b2.w;
      acc[8]+=xr[j]*c2.x; acc[9]+=xr[j]*c2.y; acc[10]+=xr[j]*c2.z; acc[11]+=xr[j]*c2.w;
    }
  }
  #pragma unroll
  for(int j=0;j<12;j++){
    int r = rg*12 + j;
    float v = acc[j];
    if(r < 4)       g_dts[(k*4+r)*L + l] = v;
    else if(r < 20) g_Bm[(k*16 + (r-4))*L + l] = v;
    else            g_Cm[(k*16 + (r-20))*L + l] = v;
  }
}

// delta: grid(ceil(L/256), 512); blockIdx.y = kd
__global__ void k_delta_v(const float* __restrict__ dtw, const float* __restrict__ dtb, int L){
  int kd = blockIdx.y;
  int k = kd >> 7;
  int l = blockIdx.x*256 + threadIdx.x;
  if(l >= L) return;
  float4 w = *(const float4*)(dtw + kd*4);
  float a = dtb[kd]
          + g_dts[(k*4+0)*L + l]*w.x + g_dts[(k*4+1)*L + l]*w.y
          + g_dts[(k*4+2)*L + l]*w.z + g_dts[(k*4+3)*L + l]*w.w;
  g_delta[kd*L + l] = softplusf(a);
}

// fused 3-pass scan: 512 thr = 32 chunks x 16 n, 2 d per THREAD. grid(64, 4).
__global__ void k_scan(const float* __restrict__ alog, int L, int H, int W){
  __shared__ float s_aP[1024], s_hE[1024], s_hI[1024];
  int tid = threadIdx.x;
  int k = blockIdx.y;
  int d0 = blockIdx.x*2, d1 = d0+1;
  int c = tid >> 4, n = tid & 15;
  int CH = L >> 5;
  float A0 = -__expf(alog[(k*128+d0)*16+n]);
  float A1 = -__expf(alog[(k*128+d1)*16+n]);
  const float* __restrict__ dl0 = g_delta + (k*128+d0)*L;
  const float* __restrict__ dl1 = g_delta + (k*128+d1)*L;
  const float* upb = (k & 1) ? g_x2 : g_x1;
  const float* __restrict__ up0 = upb + d0*L;
  const float* __restrict__ up1 = upb + d1*L;
  bool rev = (k >= 2);
  const float* __restrict__ Bp = g_Bm + (k*16+n)*L;
  const float* __restrict__ Cp = g_Cm + (k*16+n)*L;
  int l0 = c*CH;
  float h0=0.f, h1=0.f, sd0=0.f, sd1=0.f;

  if(CH >= 4){
    for(int l=l0; l<l0+CH; l+=4){
      float4 B4 = *(const float4*)(Bp+l);
      float4 D0 = *(const float4*)(dl0+l);
      float4 D1 = *(const float4*)(dl1+l);
      float4 U0, U1;
      if(!rev){ U0 = *(const float4*)(up0+l); U1 = *(const float4*)(up1+l); }
      else{
        float4 t0 = *(const float4*)(up0 + (L-4-l));
        float4 t1 = *(const float4*)(up1 + (L-4-l));
        U0 = make_float4(t0.w,t0.z,t0.y,t0.x);
        U1 = make_float4(t1.w,t1.z,t1.y,t1.x);
      }
      h0 = __expf(D0.x*A0)*h0 + D0.x*B4.x*U0.x;  h1 = __expf(D1.x*A1)*h1 + D1.x*B4.x*U1.x;
      sd0 += D0.x; sd1 += D1.x;
      h0 = __expf(D0.y*A0)*h0 + D0.y*B4.y*U0.y;  h1 = __expf(D1.y*A1)*h1 + D1.y*B4.y*U1.y;
      sd0 += D0.y; sd1 += D1.y;
      h0 = __expf(D0.z*A0)*h0 + D0.z*B4.z*U0.z;  h1 = __expf(D1.z*A1)*h1 + D1.z*B4.z*U1.z;
      sd0 += D0.z; sd1 += D1.z;
      h0 = __expf(D0.w*A0)*h0 + D0.w*B4.w*U0.w;  h1 = __expf(D1.w*A1)*h1 + D1.w*B4.w*U1.w;
      sd0 += D0.w; sd1 += D1.w;
    }
  } else {
    for(int l=l0; l<l0+CH; l++){
      int gl = rev ? (L-1-l) : l;
      float Bv = Bp[l];
      float dlt0 = dl0[l], dlt1 = dl1[l];
      float uv0 = up0[gl], uv1 = up1[gl];
      h0 = __expf(dlt0*A0)*h0 + dlt0*Bv*uv0;
      h1 = __expf(dlt1*A1)*h1 + dlt1*Bv*uv1;
      sd0 += dlt0; sd1 += dlt1;
    }
  }
  s_aP[tid]     = __expf(A0*sd0); s_hE[tid]     = h0;
  s_aP[512+tid] = __expf(A1*sd1); s_hE[512+tid] = h1;
  __syncthreads();
  if(tid < 32){
    int dg = tid >> 4, n2 = tid & 15;
    int base = dg*512 + n2;
    float hh = 0.f;
    #pragma unroll 4
    for(int c2=0;c2<32;c2++){
      int a = base + c2*16;
      s_hI[a] = hh;
      hh = s_aP[a]*hh + s_hE[a];
    }
  }
  __syncthreads();
  h0 = s_hI[tid]; h1 = s_hI[512+tid];
  float* __restrict__ ysp0 = g_ys + (k*128+d0)*L;
  float* __restrict__ ysp1 = g_ys + (k*128+d1)*L;

  if(CH >= 4){
    for(int l=l0; l<l0+CH; l+=4){
      float4 B4 = *(const float4*)(Bp+l);
      float4 C4 = *(const float4*)(Cp+l);
      float4 D0 = *(const float4*)(dl0+l);
      float4 D1 = *(const float4*)(dl1+l);
      float4 U0, U1;
      if(!rev){ U0 = *(const float4*)(up0+l); U1 = *(const float4*)(up1+l); }
      else{
        float4 t0 = *(const float4*)(up0 + (L-4-l));
        float4 t1 = *(const float4*)(up1 + (L-4-l));
        U0 = make_float4(t0.w,t0.z,t0.y,t0.x);
        U1 = make_float4(t1.w,t1.z,t1.y,t1.x);
      }
      float dv0[4] = {D0.x,D0.y,D0.z,D0.w};
      float dv1[4] = {D1.x,D1.y,D1.z,D1.w};
      float bv[4]  = {B4.x,B4.y,B4.z,B4.w};
      float cv[4]  = {C4.x,C4.y,C4.z,C4.w};
      float u0[4]  = {U0.x,U0.y,U0.z,U0.w};
      float u1[4]  = {U1.x,U1.y,U1.z,U1.w};
      #pragma unroll
      for(int j=0;j<4;j++){
        h0 = __expf(dv0[j]*A0)*h0 + dv0[j]*bv[j]*u0[j];
        h1 = __expf(dv1[j]*A1)*h1 + dv1[j]*bv[j]*u1[j];
        float pr0 = h0*cv[j], pr1 = h1*cv[j];
        pr0 += __shfl_xor_sync(0xffffffffu, pr0, 8);
        pr1 += __shfl_xor_sync(0xffffffffu, pr1, 8);
        pr0 += __shfl_xor_sync(0xffffffffu, pr0, 4);
        pr1 += __shfl_xor_sync(0xffffffffu, pr1, 4);
        pr0 += __shfl_xor_sync(0xffffffffu, pr0, 2);
        pr1 += __shfl_xor_sync(0xffffffffu, pr1, 2);
        pr0 += __shfl_xor_sync(0xffffffffu, pr0, 1);
        pr1 += __shfl_xor_sync(0xffffffffu, pr1, 1);
        if(n == 0){
          int ll = l + j;
          int pos;
          if(k == 0) pos = ll;
          else if(k == 1) pos = (ll % H)*W + ll/H;
          else if(k == 2) pos = L-1-ll;
          else { int m = L-1-ll; pos = (m % H)*W + m/H; }
          ysp0[pos] = pr0;
          ysp1[pos] = pr1;
        }
      }
    }
  } else {
    for(int l=l0; l<l0+CH; l++){
      int gl = rev ? (L-1-l) : l;
      float Bv = Bp[l], Cv = Cp[l];
      float dlt0 = dl0[l], dlt1 = dl1[l];
      float uv0 = up0[gl], uv1 = up1[gl];
      h0 = __expf(dlt0*A0)*h0 + dlt0*Bv*uv0;
      h1 = __expf(dlt1*A1)*h1 + dlt1*Bv*uv1;
      float pr0 = h0*Cv, pr1 = h1*Cv;
      pr0 += __shfl_xor_sync(0xffffffffu, pr0, 8);
      pr1 += __shfl_xor_sync(0xffffffffu, pr1, 8);
      pr0 += __shfl_xor_sync(0xffffffffu, pr0, 4);
      pr1 += __shfl_xor_sync(0xffffffffu, pr1, 4);
      pr0 += __shfl_xor_sync(0xffffffffu, pr0, 2);
      pr1 += __shfl_xor_sync(0xffffffffu, pr1, 2);
      pr0 += __shfl_xor_sync(0xffffffffu, pr0, 1);
      pr1 += __shfl_xor_sync(0xffffffffu, pr1, 1);
      if(n == 0){
        int pos;
        if(k == 0) pos = l;
        else if(k == 1) pos = (l % H)*W + l/H;
        else if(k == 2) pos = L-1-l;
        else { int m = L-1-l; pos = (m % H)*W + m/H; }
        ysp0[pos] = pr0;
        ysp1[pos] = pr1;
      }
    }
  }
}

// fused combine + out-LN + *silu(z). grid(L/32), block 256
__global__ void k_post(const float* __restrict__ Dpw, const float* __restrict__ og,
                       const float* __restrict__ ob, int L){
  __shared__ float sds[128], sog[128], sob[128];
  __shared__ float red[8*32];
  __shared__ float smu[32], srs[32];
  int tid = threadIdx.x;
  if(tid < 128){
    sds[tid] = Dpw[tid] + Dpw[128+tid] + Dpw[256+tid] + Dpw[384+tid];
    sog[tid] = og[tid]; sob[tid] = ob[tid];
  }
  __syncthreads();
  int p = tid & 31, dg = tid >> 5;
  int pp = blockIdx.x*32 + p;
  float v[16];
  float s = 0.f;
  #pragma unroll
  for(int dd=0;dd<16;dd++){
    int d = dg*16 + dd;
    float a = g_ys[d*L + pp] + g_ys[(128+d)*L + pp]
            + g_ys[(256+d)*L + pp] + g_ys[(384+d)*L + pp]
            + sds[d]*g_x1[d*L + pp];
    v[dd] = a; s += a;
  }
  red[dg*32+p] = s;
  __syncthreads();
  if(dg == 0){
    float a = 0.f;
    #pragma unroll
    for(int j=0;j<8;j++) a += red[j*32+p];
    smu[p] = a*(1.0f/128.0f);
  }
  __syncthreads();
  float mu = smu[p];
  float ss = 0.f;
  #pragma unroll
  for(int dd=0;dd<16;dd++){ float df = v[dd]-mu; ss += df*df; }
  red[dg*32+p] = ss;
  __syncthreads();
  if(dg == 0){
    float a = 0.f;
    #pragma unroll
    for(int j=0;j<8;j++) a += red[j*32+p];
    srs[p] = rsqrtf(a*(1.0f/128.0f) + 1e-6f);
  }
  __syncthreads();
  float rs = srs[p];
  #pragma unroll
  for(int dd=0;dd<16;dd++){
    int d = dg*16 + dd;
    float z = g_xz[(128+d)*L + pp];
    g_yc[d*L + pp] = ((v[dd]-mu)*rs*sog[d] + sob[d]) * siluf(z);
  }
}

// out-proj: 1 px/thread, 8 couts. grid(ceil(L/256), 8)
__global__ void k_outproj_v(const float* __restrict__ opw, int L, int skipid){
  __shared__ __align__(16) float sw[128*8];
  int tid = threadIdx.x;
  int c0 = blockIdx.y*8;
  for(int i=tid;i<1024;i+=256)
    sw[i] = opw[(i>>3)*64 + c0 + (i&7)];
  __syncthreads();
  int p = blockIdx.x*256 + tid;
  if(p >= L) return;
  float acc[8];
  #pragma unroll
  for(int c=0;c<8;c++) acc[c]=0.f;
  #pragma unroll 1
  for(int d0=0;d0<128;d0+=16){
    float yr[16];
    #pragma unroll
    for(int j=0;j<16;j++) yr[j] = g_yc[(d0+j)*L + p];
    #pragma unroll
    for(int j=0;j<16;j++){
      const float4* w4 = (const float4*)(sw + ((d0+j)<<3));
      float4 a = w4[0], b2 = w4[1];
      acc[0]+=yr[j]*a.x;  acc[1]+=yr[j]*a.y;  acc[2]+=yr[j]*a.z;  acc[3]+=yr[j]*a.w;
      acc[4]+=yr[j]*b2.x; acc[5]+=yr[j]*b2.y; acc[6]+=yr[j]*b2.z; acc[7]+=yr[j]*b2.w;
    }
  }
  float* skp = (skipid >= 0) ? bufptr(skipid) : nullptr;
  #pragma unroll
  for(int c=0;c<8;c++){
    int o = (c0+c)*L + p;
    float r = g_x[o] + acc[c];
    g_x[o] = r;
    if(skp) skp[o] = r;
  }
}

// stride-2 conv, 8-ci smem staging: out tile 8co x 8h x 16w, block 256.
// 8 sync rounds instead of 64. grid(ceil(Wo/16), ceil(Ho/8), 8)
__global__ void __launch_bounds__(256) k_conv3x3_s2(int inid, const float* __restrict__ w,
                             const float* __restrict__ b,
                             int outid, int Hi, int Wi, int Ho, int Wo){
  __shared__ float sin_[8*561];   // 8 ci planes x 17 x 33
  __shared__ float sw_[8*72];     // 8 co x (8 ci x 9)
  const float* in = bufptr(inid);
  float* out = bufptr(outid);
  int tid = threadIdx.x;
  int ox0 = blockIdx.x*16, oy0 = blockIdx.y*8;
  int cobase = blockIdx.z*8;
  int lane = tid & 31, cog = tid >> 5;     // co = cobase + cog
  int r = lane >> 2, c0 = (lane & 3)*4;    // out row 0..7, col base (4 px)
  float acc[4] = {0.f,0.f,0.f,0.f};

  for(int cig=0; cig<8; cig++){
    __syncthreads();
    for(int i=tid; i<8*561; i+=256){
      int pl = i/561, pos = i%561;
      int rr = pos/33, cc = pos%33;
      int gy = oy0*2 - 1 + rr, gx = ox0*2 - 1 + cc;
      const float* ip = in + (cig*8+pl)*Hi*Wi;
      sin_[i] = (gy>=0 && gy<Hi && gx>=0 && gx<Wi) ? ip[gy*Wi+gx] : 0.f;
    }
    for(int i=tid; i<576; i+=256){
      int co = i/72, rem = i%72;           // rem = ci_local*9 + tap
      sw_[i] = w[(cobase+co)*576 + cig*72 + rem];
    }
    __syncthreads();
    #pragma unroll
    for(int ci=0; ci<8; ci++){
      float wr[9];
      #pragma unroll
      for(int kk=0;kk<9;kk++) wr[kk] = sw_[cog*72 + ci*9 + kk];
      const float* sp = sin_ + ci*561;
      #pragma unroll
      for(int j=0;j<4;j++){
        float sa = acc[j];
        int iy = 2*r, ix = 2*(c0+j);
        #pragma unroll
        for(int di=0;di<3;di++)
          #pragma unroll
          for(int dj=0;dj<3;dj++)
            sa += wr[di*3+dj]*sp[(iy+di)*33 + ix+dj];
        acc[j] = sa;
      }
    }
  }
  int oh = oy0 + r;
  int co = cobase + cog;
  float bb = b[co];
  #pragma unroll
  for(int j=0;j<4;j++){
    int ow = ox0 + c0 + j;
    if(oh < Ho && ow < Wo)
      out[co*Ho*Wo + oh*Wo + ow] = acc[j] + bb;
  }
}

// scalar tiled conv with fused bilinear resize (fallback for small maps).
__global__ void __launch_bounds__(256) k_conv3x3_rt(int inid, const float* __restrict__ w,
                             const float* __restrict__ b,
                             int skipid, int outid, float* __restrict__ extout,
                             int Hi, int Wi, int H, int W, int dosilu){
  __shared__ float sin_[10*35];
  __shared__ float sw_[16*9];
  __shared__ int   sy0[10], sy1[10], syok[10];
  __shared__ float swy[10];
  __shared__ int   sx0[34], sx1[34], sxok[34];
  __shared__ float swx[34];
  const float* in = bufptr(inid);
  float* out = (outid < 0) ? extout : bufptr(outid);
  int tid = threadIdx.x;
  int qid = tid & 63;
  int cog = tid >> 6;
  int r   = qid >> 3;
  int q   = qid & 7;
  int ox0 = blockIdx.x*32, oy0 = blockIdx.y*8;
  int cobase = blockIdx.z*16;
  float scy = (float)Hi/(float)H, scx = (float)Wi/(float)W;

  if(tid < 10){
    int oy = oy0-1+tid;
    syok[tid] = (oy>=0 && oy<H) ? 1 : 0;
    float fy = (oy + 0.5f)*scy - 0.5f;
    int y0 = (int)floorf(fy);
    swy[tid] = fy - (float)y0;
    sy0[tid] = max(y0,0)*Wi;
    sy1[tid] = min(y0+1, Hi-1)*Wi;
  }
  if(tid >= 32 && tid < 66){
    int i = tid-32;
    int ox = ox0-1+i;
    sxok[i] = (ox>=0 && ox<W) ? 1 : 0;
    float fx = (ox + 0.5f)*scx - 0.5f;
    int x0 = (int)floorf(fx);
    swx[i] = fx - (float)x0;
    sx0[i] = max(x0,0);
    sx1[i] = min(x0+1, Wi-1);
  }

  float acc[4][4];
  #pragma unroll
  for(int i=0;i<4;i++)
    #pragma unroll
    for(int j=0;j<4;j++) acc[i][j]=0.f;

  for(int ci=0;ci<64;ci++){
    __syncthreads();
    const float* ip = in + ci*Hi*Wi;
    for(int i=tid;i<340;i+=256){
      int rr = i/34, cc = i%34;
      float v = 0.f;
      if(syok[rr] && sxok[cc]){
        float wy = swy[rr], wx = swx[cc];
        const float* r0 = ip + sy0[rr];
        const float* r1 = ip + sy1[rr];
        float a = r0[sx0[cc]], b2 = r0[sx1[cc]];
        float c2 = r1[sx0[cc]], d2 = r1[sx1[cc]];
        v = (1.f-wy)*((1.f-wx)*a + wx*b2) + wy*((1.f-wx)*c2 + wx*d2);
      }
      sin_[rr*35+cc] = v;
    }
    for(int i=tid;i<144;i+=256)
      sw_[i] = w[(cobase + i/9)*576 + ci*9 + i%9];
    __syncthreads();
    float inr[3][6];
    #pragma unroll
    for(int di=0;di<3;di++)
      #pragma unroll
      for(int dj=0;dj<6;dj++)
        inr[di][dj] = sin_[(r+di)*35 + 4*q + dj];
    #pragma unroll
    for(int co=0;co<4;co++){
      float wr[9];
      #pragma unroll
      for(int kk=0;kk<9;kk++) wr[kk] = sw_[(cog*4+co)*9 + kk];
      #pragma unroll
      for(int px=0;px<4;px++){
        float sacc = acc[co][px];
        #pragma unroll
        for(int di=0;di<3;di++)
          #pragma unroll
          for(int dj=0;dj<3;dj++)
            sacc += wr[di*3+dj]*inr[di][dj+px];
        acc[co][px] = sacc;
      }
    }
  }
  int gy = oy0 + r;
  #pragma unroll
  for(int co=0;co<4;co++){
    int c = cobase + cog*4 + co;
    float bb = b[c];
    #pragma unroll
    for(int px=0;px<4;px++){
      int gx = ox0 + 4*q + px;
      if(gy < H && gx < W){
        float v = acc[co][px] + bb;
        if(dosilu) v = siluf(v);
        int o = c*H*W + gy*W + gx;
        if(skipid >= 0) v += bufptr(skipid)[o];
        out[o] = v;
      }
    }
  }
}

// tf32 tensor-core conv3x3 + fused bilinear resize; pre-converted weights in g_wtc.
// Block 256 thr (8 warps). Output tile: 64 co x (2 rows x 32 cols). grid(W/32, H/2).
__global__ void __launch_bounds__(256) k_conv3x3_tc(int inid, int wbase,
                             const float* __restrict__ b,
                             int skipid, int outid, float* __restrict__ extout,
                             int Hi, int Wi, int H, int W, int dosilu){
  __shared__ __align__(16) uint32_t shal[8*136];
  __shared__ __align__(16) uint32_t swt[64*72];
  __shared__ int   sy0[4], sy1[4], syok[4];
  __shared__ float swy[4];
  __shared__ int   sx0[34], sx1[34], sxok[34];
  __shared__ float swx[34];
  const float* in = bufptr(inid);
  float* out = (outid < 0) ? extout : bufptr(outid);
  int tid = threadIdx.x;
  int lane = tid & 31, wid = tid >> 5;
  int mt = wid >> 1, nh = wid & 1;
  int g = lane >> 2, r0 = lane & 3;
  int ox0 = blockIdx.x*32, oy0 = blockIdx.y*2;
  float scy = (float)Hi/(float)H, scx = (float)Wi/(float)W;

  if(tid < 4){
    int oy = oy0-1+tid;
    syok[tid] = (oy>=0 && oy<H) ? 1 : 0;
    float fy = (oy + 0.5f)*scy - 0.5f;
    int y0 = (int)floorf(fy);
    swy[tid] = fy - (float)y0;
    sy0[tid] = max(y0,0)*Wi;
    sy1[tid] = min(y0+1, Hi-1)*Wi;
  }
  if(tid >= 32 && tid < 66){
    int i = tid-32;
    int ox = ox0-1+i;
    sxok[i] = (ox>=0 && ox<W) ? 1 : 0;
    float fx = (ox + 0.5f)*scx - 0.5f;
    int x0 = (int)floorf(fx);
    swx[i] = fx - (float)x0;
    sx0[i] = max(x0,0);
    sx1[i] = min(x0+1, Wi-1);
  }

  float acc[4][4];
  #pragma unroll
  for(int i=0;i<4;i++)
    #pragma unroll
    for(int j=0;j<4;j++) acc[i][j]=0.f;

  for(int cig=0; cig<8; cig++){
    __syncthreads();
    for(int i=tid;i<1088;i+=256){
      int pl = i/136, pos = i%136;
      int rr = pos/34, cc = pos%34;
      float v = 0.f;
      if(syok[rr] && sxok[cc]){
        const float* ip = in + (cig*8+pl)*Hi*Wi;
        float wy = swy[rr], wx = swx[cc];
        const float* q0 = ip + sy0[rr];
        const float* q1 = ip + sy1[rr];
        float a = q0[sx0[cc]], b2 = q0[sx1[cc]];
        float c2 = q1[sx0[cc]], d2 = q1[sx1[cc]];
        v = (1.f-wy)*((1.f-wx)*a + wx*b2) + wy*((1.f-wx)*c2 + wx*d2);
      }
      shal[i] = f2tf(v);
    }
    for(int j=tid; j<1152; j+=256){
      int i = j*4;
      int co = i/72, rem = i%72;
      *((uint4*)(swt + i)) = *((const uint4*)(g_wtc + wbase + co*576 + cig*72 + rem));
    }
    __syncthreads();
    #pragma unroll
    for(int tp=0;tp<9;tp++){
      int dy = tp/3, dx = tp%3;
      uint32_t a0 = swt[(mt*16+g)*72   + r0*9     + tp];
      uint32_t a1 = swt[(mt*16+g+8)*72 + r0*9     + tp];
      uint32_t a2 = swt[(mt*16+g)*72   + (r0+4)*9 + tp];
      uint32_t a3 = swt[(mt*16+g+8)*72 + (r0+4)*9 + tp];
      #pragma unroll
      for(int nt=0;nt<4;nt++){
        int n = (nh*4+nt)*8 + g;
        int py = n >> 5, px = n & 31;
        int addr = (py+dy)*34 + px + dx;
        uint32_t b0 = shal[r0*136 + addr];
        uint32_t b1 = shal[(r0+4)*136 + addr];
        mma_tf32(acc[nt], a0, a1, a2, a3, b0, b1);
      }
    }
  }

  float bb0 = b[mt*16+g], bb1 = b[mt*16+g+8];
  float* skp = (skipid >= 0) ? bufptr(skipid) : nullptr;
  #pragma unroll
  for(int nt=0;nt<4;nt++){
    int n0 = (nh*4+nt)*8 + r0*2;
    int py = n0 >> 5, px = n0 & 31;
    int gy = oy0 + py, gx = ox0 + px;
    #pragma unroll
    for(int half=0; half<2; half++){
      int co = mt*16 + g + half*8;
      float v0 = acc[nt][half*2+0] + (half ? bb1 : bb0);
      float v1 = acc[nt][half*2+1] + (half ? bb1 : bb0);
      if(dosilu){ v0 = siluf(v0); v1 = siluf(v1); }
      int o = co*H*W + gy*W + gx;
      if(skp){ v0 += skp[o]; v1 += skp[o+1]; }
      out[o]   = v0;
      out[o+1] = v1;
    }
  }
}

// ---------------- host orchestration ----------------
static inline int gs(int n, int bs){ return (n + bs - 1)/bs; }

extern "C" void kernel_launch(void* const* d_in, const int* in_sizes, int n_in,
                              void* d_out, int out_size){
  const float* E0     = (const float*)d_in[0];
  const float* pe_w   = (const float*)d_in[1];
  const float* pe_b   = (const float*)d_in[2];
  const float* pe_lg  = (const float*)d_in[3];
  const float* pe_lb  = (const float*)d_in[4];
  const float* ln_g   = (const float*)d_in[5];
  const float* ln_b   = (const float*)d_in[6];
  const float* in_w   = (const float*)d_in[7];
  const float* cv_w   = (const float*)d_in[8];
  const float* cv_b   = (const float*)d_in[9];
  const float* xp_w   = (const float*)d_in[10];
  const float* dt_w   = (const float*)d_in[11];
  const float* dt_b   = (const float*)d_in[12];
  const float* A_log  = (const float*)d_in[13];
  const float* Dp     = (const float*)d_in[14];
  const float* on_g   = (const float*)d_in[15];
  const float* on_b   = (const float*)d_in[16];
  const float* out_pw = (const float*)d_in[17];
  const float* dn_w   = (const float*)d_in[18];
  const float* dn_b   = (const float*)d_in[19];
  const float* dn_g   = (const float*)d_in[20];
  const float* dn_lb  = (const float*)d_in[21];
  const float* up_w   = (const float*)d_in[22];
  const float* up_b   = (const float*)d_in[23];
  const float* oc_w   = (const float*)d_in[24];
  const float* oc_b   = (const float*)d_in[25];

  const int BS = 256;

  k_patch_embed<<<gs(64*4096,BS),BS>>>(E0, pe_w, pe_b);
  k_wprep<<<576,256>>>(up_w, oc_w);
  k_ln2d_w<<<gs(4096*32,BS),BS>>>(0, 0, pe_lg, pe_lb, 4096);

  auto vss = [&](int blk, int H, int skipid){
    int W = H, L = H*W;
    k_lninproj <<<dim3(gs(L,256),16),256>>>(in_w + blk*64*256, ln_g + blk*64, ln_b + blk*64, L);
    if(W >= 32)
      k_dwconv_t<<<dim3(W/32, H/8, 128),256>>>(cv_w + blk*128*9, cv_b + blk*128, H, W);
    else
      k_dwconv_tr<<<gs(128*L,BS),BS>>>(cv_w + blk*128*9, cv_b + blk*128, H, W);
    k_xproj_v  <<<dim3(gs(L,256),4,3),256>>>(xp_w + blk*4*36*128, L);
    k_delta_v  <<<dim3(gs(L,256),512),256>>>(dt_w + blk*4*128*4, dt_b + blk*4*128, L);
    k_scan     <<<dim3(64,4),512>>>(A_log + blk*4*128*16, L, H, W);
    k_post     <<<L/32,256>>>(Dp + blk*4*128, on_g + blk*128, on_b + blk*128, L);
    k_outproj_v<<<dim3(gs(L,256),8),256>>>(out_pw + blk*128*64, L, skipid);
  };

  const int skipid[3] = {4, 5, 6};
  int H = 64;
  for(int st=0; st<4; st++){
    vss(st*2,   H, -1);
    vss(st*2+1, H, (st < 3) ? skipid[st] : -1);
    if(st < 3){
      int Ho = H/2;
      dim3 gdn(gs(Ho,16), gs(Ho,8), 8);
      k_conv3x3_s2<<<gdn,256>>>(0, dn_w + st*64*64*9, dn_b + st*64, 3, H, H, Ho, Ho);
      k_ln2d_w<<<gs(Ho*Ho*32,BS),BS>>>(3, 0, dn_g + st*64, dn_lb + st*64, Ho*Ho);
      H = Ho;
    }
  }

  int cur = 0;
  for(int i=0;i<3;i++){
    int Ho = H*2;
    int oth = (cur == 0) ? 2 : 0;
    if(Ho % 32 == 0){
      dim3 gconv(Ho/32, Ho/2);
      k_conv3x3_tc<<<gconv,256>>>(cur, i*36864, up_b + i*64,
                                  skipid[2-i], oth, nullptr, H, H, Ho, Ho, 1);
    } else {
      dim3 gconv(gs(Ho,32), gs(Ho,8), 4);
      k_conv3x3_rt<<<gconv,256>>>(cur, up_w + i*64*64*9, up_b + i*64,
                                  skipid[2-i], oth, nullptr, H, H, Ho, Ho, 1);
    }
    cur = oth;
    H = Ho;
  }

  dim3 gfin(8, 128);
  k_conv3x3_tc<<<gfin,256>>>(cur, 3*36864, oc_b, -1, -1, (float*)d_out,
                             64, 64, 256, 256, 1);
}

// round 17
// speedup vs baseline: 1.1979x; 1.0218x over previous
#include <cuda_runtime.h>
#include <math.h>
#include <stdint.h>

#define LMAX 4096
__device__ __align__(16) float g_x    [64*LMAX];
__device__ __align__(16) float g_t1   [64*256*256];
__device__ __align__(16) float g_t2   [64*128*128];
__device__ __align__(16) float g_s0   [64*4096];
__device__ __align__(16) float g_s1   [64*1024];
__device__ __align__(16) float g_s2   [64*256];
__device__ __align__(16) float g_xz   [256*LMAX];
__device__ __align__(16) float g_x1   [128*LMAX];
__device__ __align__(16) float g_x2   [128*LMAX];
__device__ __align__(16) float g_dts  [4*4*LMAX];
__device__ __align__(16) float g_Bm   [4*16*LMAX];   // [k][n][L]
__device__ __align__(16) float g_Cm   [4*16*LMAX];   // [k][n][L]
__device__ __align__(16) float g_delta[4*128*LMAX];
__device__ __align__(16) float g_ys   [4*128*LMAX];  // spatial order
__device__ __align__(16) float g_yc   [128*LMAX];
__device__ __align__(16) uint32_t g_wtc[4*64*576];   // tf32 decoder weights

__device__ __forceinline__ float* bufptr(int id){
  switch(id){
    case 0: return g_x;
    case 2: return g_t1;
    case 3: return g_t2;
    case 4: return g_s0;
    case 5: return g_s1;
    default: return g_s2;
  }
}

__device__ __forceinline__ float siluf(float x){ return x / (1.0f + __expf(-x)); }
__device__ __forceinline__ float softplusf(float x){ return (x > 20.0f) ? x : log1pf(__expf(x)); }

__device__ __forceinline__ uint32_t f2tf(float v){
  uint32_t r; asm("cvt.rna.tf32.f32 %0, %1;" : "=r"(r) : "f"(v)); return r;
}
__device__ __forceinline__ void mma_tf32(float* d, uint32_t a0, uint32_t a1, uint32_t a2,
                                         uint32_t a3, uint32_t b0, uint32_t b1){
  asm("mma.sync.aligned.m16n8k8.row.col.f32.tf32.tf32.f32 "
      "{%0,%1,%2,%3},{%4,%5,%6,%7},{%8,%9},{%0,%1,%2,%3};"
      : "+f"(d[0]),"+f"(d[1]),"+f"(d[2]),"+f"(d[3])
      : "r"(a0),"r"(a1),"r"(a2),"r"(a3),"r"(b0),"r"(b1));
}

// ---------------- kernels ----------------

__global__ void k_patch_embed(const float* __restrict__ E0, const float* __restrict__ w,
                              const float* __restrict__ b){
  int idx = blockIdx.x*blockDim.x + threadIdx.x;
  if(idx >= 64*4096) return;
  int c = idx >> 12, p = idx & 4095;
  int oh = p >> 6, ow = p & 63;
  const float* wp = w + c*16;
  float acc = b[c];
  #pragma unroll
  for(int i=0;i<4;i++)
    #pragma unroll
    for(int j=0;j<4;j++)
      acc += E0[(oh*4+i)*256 + ow*4 + j] * wp[i*4+j];
  g_x[idx] = acc;
}

// precompute tf32 decoder weights: [0..2]=up_w convs, [3]=oc_w
__global__ void k_wprep(const float* __restrict__ upw, const float* __restrict__ ocw){
  int i = blockIdx.x*256 + threadIdx.x;
  if(i < 3*36864) g_wtc[i] = f2tf(upw[i]);
  else if(i < 4*36864) g_wtc[i] = f2tf(ocw[i - 3*36864]);
}

// warp-per-pixel LN over 64 channels (stage transitions)
__global__ void k_ln2d_w(int inid, int outid, const float* __restrict__ g,
                         const float* __restrict__ b, int L){
  int gid = (blockIdx.x*blockDim.x + threadIdx.x) >> 5;
  int lane = threadIdx.x & 31;
  if(gid >= L) return;
  const float* in = bufptr(inid);
  float* out = bufptr(outid);
  float v0 = in[lane*L + gid], v1 = in[(lane+32)*L + gid];
  float s = v0 + v1;
  #pragma unroll
  for(int o=16;o>0;o>>=1) s += __shfl_xor_sync(0xffffffffu, s, o);
  float mu = s*(1.0f/64.0f);
  float d0 = v0-mu, d1 = v1-mu;
  float q = d0*d0 + d1*d1;
  #pragma unroll
  for(int o=16;o>0;o>>=1) q += __shfl_xor_sync(0xffffffffu, q, o);
  float rs = rsqrtf(q*(1.0f/64.0f) + 1e-6f);
  out[lane*L + gid]      = d0*rs*g[lane]    + b[lane];
  out[(lane+32)*L + gid] = d1*rs*g[lane+32] + b[lane+32];
}

// fused LN + in-proj: 1 px/thread, 8 e per thread. grid(ceil(L/256), 32)
__global__ void __launch_bounds__(256) k_lninproj(const float* __restrict__ inw,
                        const float* __restrict__ lng, const float* __restrict__ lnb, int L){
  __shared__ __align__(16) float sw[64*8];
  __shared__ float sg[64], sb[64];
  int tid = threadIdx.x;
  int e0 = blockIdx.y*8;
  for(int i=tid;i<512;i+=256) sw[i] = inw[(i>>3)*256 + e0 + (i&7)];
  if(tid < 64){ sg[tid]=lng[tid]; sb[tid]=lnb[tid]; }
  __syncthreads();
  int p = blockIdx.x*256 + tid;
  if(p >= L) return;
  float xr[64];
  #pragma unroll
  for(int c=0;c<64;c++) xr[c] = g_x[c*L+p];
  float mu = 0.f;
  #pragma unroll
  for(int c=0;c<64;c++) mu += xr[c];
  mu *= (1.0f/64.0f);
  float var = 0.f;
  #pragma unroll
  for(int c=0;c<64;c++){ float d = xr[c]-mu; var += d*d; }
  float rs = rsqrtf(var*(1.0f/64.0f) + 1e-6f);
  float acc[8];
  #pragma unroll
  for(int e=0;e<8;e++) acc[e]=0.f;
  #pragma unroll
  for(int c=0;c<64;c++){
    float h = (xr[c]-mu)*rs*sg[c] + sb[c];
    const float4* w4 = (const float4*)(sw + (c<<3));
    #pragma unroll
    for(int j=0;j<2;j++){
      float4 v = w4[j];
      acc[4*j+0] += h*v.x; acc[4*j+1] += h*v.y;
      acc[4*j+2] += h*v.z; acc[4*j+3] += h*v.w;
    }
  }
  #pragma unroll
  for(int e=0;e<8;e++)
    g_xz[(e0+e)*L + p] = acc[e];
}

// tiled depthwise 3x3 + silu; coalesced writes for BOTH orientations.
// grid(W/32, H/8, 128), block 256.
__global__ void k_dwconv_t(const float* __restrict__ w, const float* __restrict__ b,
                           int H, int W){
  __shared__ float sin_[10*34];
  __shared__ float sout[8*33];
  int L = H*W;
  int tid = threadIdx.x;
  int d = blockIdx.z;
  int x0 = blockIdx.x*32, y0 = blockIdx.y*8;
  const float* in = g_xz + d*L;
  for(int i=tid;i<340;i+=256){
    int rr = i/34, cc = i%34;
    int gy = y0-1+rr, gx = x0-1+cc;
    sin_[rr*34+cc] = (gy>=0 && gy<H && gx>=0 && gx<W) ? in[gy*W+gx] : 0.f;
  }
  float wr[9];
  #pragma unroll
  for(int kk=0;kk<9;kk++) wr[kk] = w[d*9+kk];
  __syncthreads();
  int r = tid >> 5, q = tid & 31;
  float acc = b[d];
  #pragma unroll
  for(int di=0;di<3;di++)
    #pragma unroll
    for(int dj=0;dj<3;dj++)
      acc += sin_[(r+di)*34 + q+dj]*wr[di*3+dj];
  float v = siluf(acc);
  g_x1[d*L + (y0+r)*W + x0+q] = v;
  sout[r*33+q] = v;
  __syncthreads();
  int ww = tid >> 3, hr = tid & 7;
  g_x2[d*L + (x0+ww)*H + (y0+hr)] = sout[hr*33+ww];
}

// fallback dwconv for small maps
__global__ void k_dwconv_tr(const float* __restrict__ w, const float* __restrict__ b,
                            int H, int W){
  int L = H*W;
  int idx = blockIdx.x*blockDim.x + threadIdx.x;
  if(idx >= 128*L) return;
  int d = idx / L, p = idx % L;
  int hh = p / W, ww = p % W;
  const float* in = g_xz + d*L;
  const float* wp = w + d*9;
  float acc = b[d];
  #pragma unroll
  for(int i=-1;i<=1;i++){
    int ih = hh+i; if(ih<0 || ih>=H) continue;
    #pragma unroll
    for(int j=-1;j<=1;j++){
      int iw = ww+j; if(iw<0 || iw>=W) continue;
      acc += in[ih*W+iw]*wp[(i+1)*3+(j+1)];
    }
  }
  float v = siluf(acc);
  g_x1[idx] = v;
  g_x2[d*L + ww*H + hh] = v;
}

// x-proj: 1 l/thread, 6 r per thread. grid(ceil(L/256), 4, 6)
__global__ void __launch_bounds__(256) k_xproj_v(const float* __restrict__ xpw, int L){
  __shared__ __align__(16) float sw[128*6];
  int tid = threadIdx.x;
  int k = blockIdx.y, rg = blockIdx.z;
  for(int i=tid;i<768;i+=256){
    int d = i/6, j = i%6;
    sw[i] = xpw[k*4608 + (rg*6+j)*128 + d];
  }
  __syncthreads();
  int l = blockIdx.x*256 + tid;
  if(l >= L) return;
  int gl = (k >= 2) ? (L-1-l) : l;
  const float* base = ((k & 1) ? g_x2 : g_x1) + gl;
  float acc[6];
  #pragma unroll
  for(int j=0;j<6;j++) acc[j]=0.f;
  #pragma unroll 1
  for(int c0=0;c0<128;c0+=16){
    float xr[16];
    #pragma unroll
    for(int j=0;j<16;j++) xr[j] = base[(c0+j)*L];
    #pragma unroll
    for(int j=0;j<16;j++){
      const float2* w2 = (const float2*)(sw + (c0+j)*6);
      float2 a = w2[0], b2 = w2[1], c2 = w2[2];
      acc[0]+=xr[j]*a.x;  acc[1]+=xr[j]*a.y;
      acc[2]+=xr[j]*b2.x; acc[3]+=xr[j]*b2.y;
      acc[4]+=xr[j]*c2.x; acc[5]+=xr[j]*c2.y;
    }
  }
  #pragma unroll
  for(int j=0;j<6;j++){
    int r = rg*6 + j;
    float v = acc[j];
    if(r < 4)       g_dts[(k*4+r)*L + l] = v;
    else if(r < 20) g_Bm[(k*16 + (r-4))*L + l] = v;
    else            g_Cm[(k*16 + (r-20))*L + l] = v;
  }
}

// delta: grid(ceil(L/256), 512); blockIdx.y = kd
__global__ void k_delta_v(const float* __restrict__ dtw, const float* __restrict__ dtb, int L){
  int kd = blockIdx.y;
  int k = kd >> 7;
  int l = blockIdx.x*256 + threadIdx.x;
  if(l >= L) return;
  float4 w = *(const float4*)(dtw + kd*4);
  float a = dtb[kd]
          + g_dts[(k*4+0)*L + l]*w.x + g_dts[(k*4+1)*L + l]*w.y
          + g_dts[(k*4+2)*L + l]*w.z + g_dts[(k*4+3)*L + l]*w.w;
  g_delta[kd*L + l] = softplusf(a);
}

// fused 3-pass scan: 512 thr = 32 chunks x 16 n, 2 d per THREAD. grid(64, 4).
__global__ void k_scan(const float* __restrict__ alog, int L, int H, int W){
  __shared__ float s_aP[1024], s_hE[1024], s_hI[1024];
  int tid = threadIdx.x;
  int k = blockIdx.y;
  int d0 = blockIdx.x*2, d1 = d0+1;
  int c = tid >> 4, n = tid & 15;
  int CH = L >> 5;
  float A0 = -__expf(alog[(k*128+d0)*16+n]);
  float A1 = -__expf(alog[(k*128+d1)*16+n]);
  const float* __restrict__ dl0 = g_delta + (k*128+d0)*L;
  const float* __restrict__ dl1 = g_delta + (k*128+d1)*L;
  const float* upb = (k & 1) ? g_x2 : g_x1;
  const float* __restrict__ up0 = upb + d0*L;
  const float* __restrict__ up1 = upb + d1*L;
  bool rev = (k >= 2);
  const float* __restrict__ Bp = g_Bm + (k*16+n)*L;
  const float* __restrict__ Cp = g_Cm + (k*16+n)*L;
  int l0 = c*CH;
  float h0=0.f, h1=0.f, sd0=0.f, sd1=0.f;

  if(CH >= 4){
    for(int l=l0; l<l0+CH; l+=4){
      float4 B4 = *(const float4*)(Bp+l);
      float4 D0 = *(const float4*)(dl0+l);
      float4 D1 = *(const float4*)(dl1+l);
      float4 U0, U1;
      if(!rev){ U0 = *(const float4*)(up0+l); U1 = *(const float4*)(up1+l); }
      else{
        float4 t0 = *(const float4*)(up0 + (L-4-l));
        float4 t1 = *(const float4*)(up1 + (L-4-l));
        U0 = make_float4(t0.w,t0.z,t0.y,t0.x);
        U1 = make_float4(t1.w,t1.z,t1.y,t1.x);
      }
      h0 = __expf(D0.x*A0)*h0 + D0.x*B4.x*U0.x;  h1 = __expf(D1.x*A1)*h1 + D1.x*B4.x*U1.x;
      sd0 += D0.x; sd1 += D1.x;
      h0 = __expf(D0.y*A0)*h0 + D0.y*B4.y*U0.y;  h1 = __expf(D1.y*A1)*h1 + D1.y*B4.y*U1.y;
      sd0 += D0.y; sd1 += D1.y;
      h0 = __expf(D0.z*A0)*h0 + D0.z*B4.z*U0.z;  h1 = __expf(D1.z*A1)*h1 + D1.z*B4.z*U1.z;
      sd0 += D0.z; sd1 += D1.z;
      h0 = __expf(D0.w*A0)*h0 + D0.w*B4.w*U0.w;  h1 = __expf(D1.w*A1)*h1 + D1.w*B4.w*U1.w;
      sd0 += D0.w; sd1 += D1.w;
    }
  } else {
    for(int l=l0; l<l0+CH; l++){
      int gl = rev ? (L-1-l) : l;
      float Bv = Bp[l];
      float dlt0 = dl0[l], dlt1 = dl1[l];
      float uv0 = up0[gl], uv1 = up1[gl];
      h0 = __expf(dlt0*A0)*h0 + dlt0*Bv*uv0;
      h1 = __expf(dlt1*A1)*h1 + dlt1*Bv*uv1;
      sd0 += dlt0; sd1 += dlt1;
    }
  }
  s_aP[tid]     = __expf(A0*sd0); s_hE[tid]     = h0;
  s_aP[512+tid] = __expf(A1*sd1); s_hE[512+tid] = h1;
  __syncthreads();
  if(tid < 32){
    int dg = tid >> 4, n2 = tid & 15;
    int base = dg*512 + n2;
    float hh = 0.f;
    #pragma unroll 4
    for(int c2=0;c2<32;c2++){
      int a = base + c2*16;
      s_hI[a] = hh;
      hh = s_aP[a]*hh + s_hE[a];
    }
  }
  __syncthreads();
  h0 = s_hI[tid]; h1 = s_hI[512+tid];
  float* __restrict__ ysp0 = g_ys + (k*128+d0)*L;
  float* __restrict__ ysp1 = g_ys + (k*128+d1)*L;

  if(CH >= 4){
    for(int l=l0; l<l0+CH; l+=4){
      float4 B4 = *(const float4*)(Bp+l);
      float4 C4 = *(const float4*)(Cp+l);
      float4 D0 = *(const float4*)(dl0+l);
      float4 D1 = *(const float4*)(dl1+l);
      float4 U0, U1;
      if(!rev){ U0 = *(const float4*)(up0+l); U1 = *(const float4*)(up1+l); }
      else{
        float4 t0 = *(const float4*)(up0 + (L-4-l));
        float4 t1 = *(const float4*)(up1 + (L-4-l));
        U0 = make_float4(t0.w,t0.z,t0.y,t0.x);
        U1 = make_float4(t1.w,t1.z,t1.y,t1.x);
      }
      float dv0[4] = {D0.x,D0.y,D0.z,D0.w};
      float dv1[4] = {D1.x,D1.y,D1.z,D1.w};
      float bv[4]  = {B4.x,B4.y,B4.z,B4.w};
      float cv[4]  = {C4.x,C4.y,C4.z,C4.w};
      float u0[4]  = {U0.x,U0.y,U0.z,U0.w};
      float u1[4]  = {U1.x,U1.y,U1.z,U1.w};
      #pragma unroll
      for(int j=0;j<4;j++){
        h0 = __expf(dv0[j]*A0)*h0 + dv0[j]*bv[j]*u0[j];
        h1 = __expf(dv1[j]*A1)*h1 + dv1[j]*bv[j]*u1[j];
        float pr0 = h0*cv[j], pr1 = h1*cv[j];
        pr0 += __shfl_xor_sync(0xffffffffu, pr0, 8);
        pr1 += __shfl_xor_sync(0xffffffffu, pr1, 8);
        pr0 += __shfl_xor_sync(0xffffffffu, pr0, 4);
        pr1 += __shfl_xor_sync(0xffffffffu, pr1, 4);
        pr0 += __shfl_xor_sync(0xffffffffu, pr0, 2);
        pr1 += __shfl_xor_sync(0xffffffffu, pr1, 2);
        pr0 += __shfl_xor_sync(0xffffffffu, pr0, 1);
        pr1 += __shfl_xor_sync(0xffffffffu, pr1, 1);
        if(n == 0){
          int ll = l + j;
          int pos;
          if(k == 0) pos = ll;
          else if(k == 1) pos = (ll % H)*W + ll/H;
          else if(k == 2) pos = L-1-ll;
          else { int m = L-1-ll; pos = (m % H)*W + m/H; }
          ysp0[pos] = pr0;
          ysp1[pos] = pr1;
        }
      }
    }
  } else {
    for(int l=l0; l<l0+CH; l++){
      int gl = rev ? (L-1-l) : l;
      float Bv = Bp[l], Cv = Cp[l];
      float dlt0 = dl0[l], dlt1 = dl1[l];
      float uv0 = up0[gl], uv1 = up1[gl];
      h0 = __expf(dlt0*A0)*h0 + dlt0*Bv*uv0;
      h1 = __expf(dlt1*A1)*h1 + dlt1*Bv*uv1;
      float pr0 = h0*Cv, pr1 = h1*Cv;
      pr0 += __shfl_xor_sync(0xffffffffu, pr0, 8);
      pr1 += __shfl_xor_sync(0xffffffffu, pr1, 8);
      pr0 += __shfl_xor_sync(0xffffffffu, pr0, 4);
      pr1 += __shfl_xor_sync(0xffffffffu, pr1, 4);
      pr0 += __shfl_xor_sync(0xffffffffu, pr0, 2);
      pr1 += __shfl_xor_sync(0xffffffffu, pr1, 2);
      pr0 += __shfl_xor_sync(0xffffffffu, pr0, 1);
      pr1 += __shfl_xor_sync(0xffffffffu, pr1, 1);
      if(n == 0){
        int pos;
        if(k == 0) pos = l;
        else if(k == 1) pos = (l % H)*W + l/H;
        else if(k == 2) pos = L-1-l;
        else { int m = L-1-l; pos = (m % H)*W + m/H; }
        ysp0[pos] = pr0;
        ysp1[pos] = pr1;
      }
    }
  }
}

// fused combine + out-LN + *silu(z). grid(L/32), block 256
__global__ void k_post(const float* __restrict__ Dpw, const float* __restrict__ og,
                       const float* __restrict__ ob, int L){
  __shared__ float sds[128], sog[128], sob[128];
  __shared__ float red[8*32];
  __shared__ float smu[32], srs[32];
  int tid = threadIdx.x;
  if(tid < 128){
    sds[tid] = Dpw[tid] + Dpw[128+tid] + Dpw[256+tid] + Dpw[384+tid];
    sog[tid] = og[tid]; sob[tid] = ob[tid];
  }
  __syncthreads();
  int p = tid & 31, dg = tid >> 5;
  int pp = blockIdx.x*32 + p;
  float v[16];
  float s = 0.f;
  #pragma unroll
  for(int dd=0;dd<16;dd++){
    int d = dg*16 + dd;
    float a = g_ys[d*L + pp] + g_ys[(128+d)*L + pp]
            + g_ys[(256+d)*L + pp] + g_ys[(384+d)*L + pp]
            + sds[d]*g_x1[d*L + pp];
    v[dd] = a; s += a;
  }
  red[dg*32+p] = s;
  __syncthreads();
  if(dg == 0){
    float a = 0.f;
    #pragma unroll
    for(int j=0;j<8;j++) a += red[j*32+p];
    smu[p] = a*(1.0f/128.0f);
  }
  __syncthreads();
  float mu = smu[p];
  float ss = 0.f;
  #pragma unroll
  for(int dd=0;dd<16;dd++){ float df = v[dd]-mu; ss += df*df; }
  red[dg*32+p] = ss;
  __syncthreads();
  if(dg == 0){
    float a = 0.f;
    #pragma unroll
    for(int j=0;j<8;j++) a += red[j*32+p];
    srs[p] = rsqrtf(a*(1.0f/128.0f) + 1e-6f);
  }
  __syncthreads();
  float rs = srs[p];
  #pragma unroll
  for(int dd=0;dd<16;dd++){
    int d = dg*16 + dd;
    float z = g_xz[(128+d)*L + pp];
    g_yc[d*L + pp] = ((v[dd]-mu)*rs*sog[d] + sob[d]) * siluf(z);
  }
}

// out-proj: 1 px/thread, 4 couts. grid(ceil(L/256), 16)
__global__ void k_outproj_v(const float* __restrict__ opw, int L, int skipid){
  __shared__ __align__(16) float sw[128*4];
  int tid = threadIdx.x;
  int c0 = blockIdx.y*4;
  for(int i=tid;i<512;i+=256)
    sw[i] = opw[(i>>2)*64 + c0 + (i&3)];
  __syncthreads();
  int p = blockIdx.x*256 + tid;
  if(p >= L) return;
  float acc[4];
  #pragma unroll
  for(int c=0;c<4;c++) acc[c]=0.f;
  #pragma unroll 1
  for(int d0=0;d0<128;d0+=16){
    float yr[16];
    #pragma unroll
    for(int j=0;j<16;j++) yr[j] = g_yc[(d0+j)*L + p];
    #pragma unroll
    for(int j=0;j<16;j++){
      const float4* w4 = (const float4*)(sw + ((d0+j)<<2));
      float4 a = w4[0];
      acc[0]+=yr[j]*a.x;  acc[1]+=yr[j]*a.y;  acc[2]+=yr[j]*a.z;  acc[3]+=yr[j]*a.w;
    }
  }
  float* skp = (skipid >= 0) ? bufptr(skipid) : nullptr;
  #pragma unroll
  for(int c=0;c<4;c++){
    int o = (c0+c)*L + p;
    float r = g_x[o] + acc[c];
    g_x[o] = r;
    if(skp) skp[o] = r;
  }
}

// stride-2 conv, 8-ci smem staging: out tile 8co x 8h x 16w, block 256.
// grid(ceil(Wo/16), ceil(Ho/8), 8)
__global__ void __launch_bounds__(256) k_conv3x3_s2(int inid, const float* __restrict__ w,
                             const float* __restrict__ b,
                             int outid, int Hi, int Wi, int Ho, int Wo){
  __shared__ float sin_[8*561];   // 8 ci planes x 17 x 33
  __shared__ float sw_[8*72];     // 8 co x (8 ci x 9)
  const float* in = bufptr(inid);
  float* out = bufptr(outid);
  int tid = threadIdx.x;
  int ox0 = blockIdx.x*16, oy0 = blockIdx.y*8;
  int cobase = blockIdx.z*8;
  int lane = tid & 31, cog = tid >> 5;
  int r = lane >> 2, c0 = (lane & 3)*4;
  float acc[4] = {0.f,0.f,0.f,0.f};

  for(int cig=0; cig<8; cig++){
    __syncthreads();
    for(int i=tid; i<8*561; i+=256){
      int pl = i/561, pos = i%561;
      int rr = pos/33, cc = pos%33;
      int gy = oy0*2 - 1 + rr, gx = ox0*2 - 1 + cc;
      const float* ip = in + (cig*8+pl)*Hi*Wi;
      sin_[i] = (gy>=0 && gy<Hi && gx>=0 && gx<Wi) ? ip[gy*Wi+gx] : 0.f;
    }
    for(int i=tid; i<576; i+=256){
      int co = i/72, rem = i%72;
      sw_[i] = w[(cobase+co)*576 + cig*72 + rem];
    }
    __syncthreads();
    #pragma unroll
    for(int ci=0; ci<8; ci++){
      float wr[9];
      #pragma unroll
      for(int kk=0;kk<9;kk++) wr[kk] = sw_[cog*72 + ci*9 + kk];
      const float* sp = sin_ + ci*561;
      #pragma unroll
      for(int j=0;j<4;j++){
        float sa = acc[j];
        int iy = 2*r, ix = 2*(c0+j);
        #pragma unroll
        for(int di=0;di<3;di++)
          #pragma unroll
          for(int dj=0;dj<3;dj++)
            sa += wr[di*3+dj]*sp[(iy+di)*33 + ix+dj];
        acc[j] = sa;
      }
    }
  }
  int oh = oy0 + r;
  int co = cobase + cog;
  float bb = b[co];
  #pragma unroll
  for(int j=0;j<4;j++){
    int ow = ox0 + c0 + j;
    if(oh < Ho && ow < Wo)
      out[co*Ho*Wo + oh*Wo + ow] = acc[j] + bb;
  }
}

// scalar tiled conv with fused bilinear resize (fallback for small maps).
__global__ void __launch_bounds__(256) k_conv3x3_rt(int inid, const float* __restrict__ w,
                             const float* __restrict__ b,
                             int skipid, int outid, float* __restrict__ extout,
                             int Hi, int Wi, int H, int W, int dosilu){
  __shared__ float sin_[10*35];
  __shared__ float sw_[16*9];
  __shared__ int   sy0[10], sy1[10], syok[10];
  __shared__ float swy[10];
  __shared__ int   sx0[34], sx1[34], sxok[34];
  __shared__ float swx[34];
  const float* in = bufptr(inid);
  float* out = (outid < 0) ? extout : bufptr(outid);
  int tid = threadIdx.x;
  int qid = tid & 63;
  int cog = tid >> 6;
  int r   = qid >> 3;
  int q   = qid & 7;
  int ox0 = blockIdx.x*32, oy0 = blockIdx.y*8;
  int cobase = blockIdx.z*16;
  float scy = (float)Hi/(float)H, scx = (float)Wi/(float)W;

  if(tid < 10){
    int oy = oy0-1+tid;
    syok[tid] = (oy>=0 && oy<H) ? 1 : 0;
    float fy = (oy + 0.5f)*scy - 0.5f;
    int y0 = (int)floorf(fy);
    swy[tid] = fy - (float)y0;
    sy0[tid] = max(y0,0)*Wi;
    sy1[tid] = min(y0+1, Hi-1)*Wi;
  }
  if(tid >= 32 && tid < 66){
    int i = tid-32;
    int ox = ox0-1+i;
    sxok[i] = (ox>=0 && ox<W) ? 1 : 0;
    float fx = (ox + 0.5f)*scx - 0.5f;
    int x0 = (int)floorf(fx);
    swx[i] = fx - (float)x0;
    sx0[i] = max(x0,0);
    sx1[i] = min(x0+1, Wi-1);
  }

  float acc[4][4];
  #pragma unroll
  for(int i=0;i<4;i++)
    #pragma unroll
    for(int j=0;j<4;j++) acc[i][j]=0.f;

  for(int ci=0;ci<64;ci++){
    __syncthreads();
    const float* ip = in + ci*Hi*Wi;
    for(int i=tid;i<340;i+=256){
      int rr = i/34, cc = i%34;
      float v = 0.f;
      if(syok[rr] && sxok[cc]){
        float wy = swy[rr], wx = swx[cc];
        const float* r0 = ip + sy0[rr];
        const float* r1 = ip + sy1[rr];
        float a = r0[sx0[cc]], b2 = r0[sx1[cc]];
        float c2 = r1[sx0[cc]], d2 = r1[sx1[cc]];
        v = (1.f-wy)*((1.f-wx)*a + wx*b2) + wy*((1.f-wx)*c2 + wx*d2);
      }
      sin_[rr*35+cc] = v;
    }
    for(int i=tid;i<144;i+=256)
      sw_[i] = w[(cobase + i/9)*576 + ci*9 + i%9];
    __syncthreads();
    float inr[3][6];
    #pragma unroll
    for(int di=0;di<3;di++)
      #pragma unroll
      for(int dj=0;dj<6;dj++)
        inr[di][dj] = sin_[(r+di)*35 + 4*q + dj];
    #pragma unroll
    for(int co=0;co<4;co++){
      float wr[9];
      #pragma unroll
      for(int kk=0;kk<9;kk++) wr[kk] = sw_[(cog*4+co)*9 + kk];
      #pragma unroll
      for(int px=0;px<4;px++){
        float sacc = acc[co][px];
        #pragma unroll
        for(int di=0;di<3;di++)
          #pragma unroll
          for(int dj=0;dj<3;dj++)
            sacc += wr[di*3+dj]*inr[di][dj+px];
        acc[co][px] = sacc;
      }
    }
  }
  int gy = oy0 + r;
  #pragma unroll
  for(int co=0;co<4;co++){
    int c = cobase + cog*4 + co;
    float bb = b[c];
    #pragma unroll
    for(int px=0;px<4;px++){
      int gx = ox0 + 4*q + px;
      if(gy < H && gx < W){
        float v = acc[co][px] + bb;
        if(dosilu) v = siluf(v);
        int o = c*H*W + gy*W + gx;
        if(skipid >= 0) v += bufptr(skipid)[o];
        out[o] = v;
      }
    }
  }
}

// tf32 tensor-core conv3x3 + fused bilinear resize; pre-converted weights in g_wtc.
// Block 256 thr (8 warps). Output tile: 64 co x (2 rows x 32 cols). grid(W/32, H/2).
__global__ void __launch_bounds__(256) k_conv3x3_tc(int inid, int wbase,
                             const float* __restrict__ b,
                             int skipid, int outid, float* __restrict__ extout,
                             int Hi, int Wi, int H, int W, int dosilu){
  __shared__ __align__(16) uint32_t shal[8*136];
  __shared__ __align__(16) uint32_t swt[64*72];
  __shared__ int   sy0[4], sy1[4], syok[4];
  __shared__ float swy[4];
  __shared__ int   sx0[34], sx1[34], sxok[34];
  __shared__ float swx[34];
  const float* in = bufptr(inid);
  float* out = (outid < 0) ? extout : bufptr(outid);
  int tid = threadIdx.x;
  int lane = tid & 31, wid = tid >> 5;
  int mt = wid >> 1, nh = wid & 1;
  int g = lane >> 2, r0 = lane & 3;
  int ox0 = blockIdx.x*32, oy0 = blockIdx.y*2;
  float scy = (float)Hi/(float)H, scx = (float)Wi/(float)W;

  if(tid < 4){
    int oy = oy0-1+tid;
    syok[tid] = (oy>=0 && oy<H) ? 1 : 0;
    float fy = (oy + 0.5f)*scy - 0.5f;
    int y0 = (int)floorf(fy);
    swy[tid] = fy - (float)y0;
    sy0[tid] = max(y0,0)*Wi;
    sy1[tid] = min(y0+1, Hi-1)*Wi;
  }
  if(tid >= 32 && tid < 66){
    int i = tid-32;
    int ox = ox0-1+i;
    sxok[i] = (ox>=0 && ox<W) ? 1 : 0;
    float fx = (ox + 0.5f)*scx - 0.5f;
    int x0 = (int)floorf(fx);
    swx[i] = fx - (float)x0;
    sx0[i] = max(x0,0);
    sx1[i] = min(x0+1, Wi-1);
  }

  float acc[4][4];
  #pragma unroll
  for(int i=0;i<4;i++)
    #pragma unroll
    for(int j=0;j<4;j++) acc[i][j]=0.f;

  for(int cig=0; cig<8; cig++){
    __syncthreads();
    for(int i=tid;i<1088;i+=256){
      int pl = i/136, pos = i%136;
      int rr = pos/34, cc = pos%34;
      float v = 0.f;
      if(syok[rr] && sxok[cc]){
        const float* ip = in + (cig*8+pl)*Hi*Wi;
        float wy = swy[rr], wx = swx[cc];
        const float* q0 = ip + sy0[rr];
        const float* q1 = ip + sy1[rr];
        float a = q0[sx0[cc]], b2 = q0[sx1[cc]];
        float c2 = q1[sx0[cc]], d2 = q1[sx1[cc]];
        v = (1.f-wy)*((1.f-wx)*a + wx*b2) + wy*((1.f-wx)*c2 + wx*d2);
      }
      shal[i] = f2tf(v);
    }
    for(int j=tid; j<1152; j+=256){
      int i = j*4;
      int co = i/72, rem = i%72;
      *((uint4*)(swt + i)) = *((const uint4*)(g_wtc + wbase + co*576 + cig*72 + rem));
    }
    __syncthreads();
    #pragma unroll
    for(int tp=0;tp<9;tp++){
      int dy = tp/3, dx = tp%3;
      uint32_t a0 = swt[(mt*16+g)*72   + r0*9     + tp];
      uint32_t a1 = swt[(mt*16+g+8)*72 + r0*9     + tp];
      uint32_t a2 = swt[(mt*16+g)*72   + (r0+4)*9 + tp];
      uint32_t a3 = swt[(mt*16+g+8)*72 + (r0+4)*9 + tp];
      #pragma unroll
      for(int nt=0;nt<4;nt++){
        int n = (nh*4+nt)*8 + g;
        int py = n >> 5, px = n & 31;
        int addr = (py+dy)*34 + px + dx;
        uint32_t b0 = shal[r0*136 + addr];
        uint32_t b1 = shal[(r0+4)*136 + addr];
        mma_tf32(acc[nt], a0, a1, a2, a3, b0, b1);
      }
    }
  }

  float bb0 = b[mt*16+g], bb1 = b[mt*16+g+8];
  float* skp = (skipid >= 0) ? bufptr(skipid) : nullptr;
  #pragma unroll
  for(int nt=0;nt<4;nt++){
    int n0 = (nh*4+nt)*8 + r0*2;
    int py = n0 >> 5, px = n0 & 31;
    int gy = oy0 + py, gx = ox0 + px;
    #pragma unroll
    for(int half=0; half<2; half++){
      int co = mt*16 + g + half*8;
      float v0 = acc[nt][half*2+0] + (half ? bb1 : bb0);
      float v1 = acc[nt][half*2+1] + (half ? bb1 : bb0);
      if(dosilu){ v0 = siluf(v0); v1 = siluf(v1); }
      int o = co*H*W + gy*W + gx;
      if(skp){ v0 += skp[o]; v1 += skp[o+1]; }
      out[o]   = v0;
      out[o+1] = v1;
    }
  }
}

// ---------------- host orchestration ----------------
static inline int gs(int n, int bs){ return (n + bs - 1)/bs; }

extern "C" void kernel_launch(void* const* d_in, const int* in_sizes, int n_in,
                              void* d_out, int out_size){
  const float* E0     = (const float*)d_in[0];
  const float* pe_w   = (const float*)d_in[1];
  const float* pe_b   = (const float*)d_in[2];
  const float* pe_lg  = (const float*)d_in[3];
  const float* pe_lb  = (const float*)d_in[4];
  const float* ln_g   = (const float*)d_in[5];
  const float* ln_b   = (const float*)d_in[6];
  const float* in_w   = (const float*)d_in[7];
  const float* cv_w   = (const float*)d_in[8];
  const float* cv_b   = (const float*)d_in[9];
  const float* xp_w   = (const float*)d_in[10];
  const float* dt_w   = (const float*)d_in[11];
  const float* dt_b   = (const float*)d_in[12];
  const float* A_log  = (const float*)d_in[13];
  const float* Dp     = (const float*)d_in[14];
  const float* on_g   = (const float*)d_in[15];
  const float* on_b   = (const float*)d_in[16];
  const float* out_pw = (const float*)d_in[17];
  const float* dn_w   = (const float*)d_in[18];
  const float* dn_b   = (const float*)d_in[19];
  const float* dn_g   = (const float*)d_in[20];
  const float* dn_lb  = (const float*)d_in[21];
  const float* up_w   = (const float*)d_in[22];
  const float* up_b   = (const float*)d_in[23];
  const float* oc_w   = (const float*)d_in[24];
  const float* oc_b   = (const float*)d_in[25];

  const int BS = 256;

  k_patch_embed<<<gs(64*4096,BS),BS>>>(E0, pe_w, pe_b);
  k_wprep<<<576,256>>>(up_w, oc_w);
  k_ln2d_w<<<gs(4096*32,BS),BS>>>(0, 0, pe_lg, pe_lb, 4096);

  auto vss = [&](int blk, int H, int skipid){
    int W = H, L = H*W;
    k_lninproj <<<dim3(gs(L,256),32),256>>>(in_w + blk*64*256, ln_g + blk*64, ln_b + blk*64, L);
    if(W >= 32)
      k_dwconv_t<<<dim3(W/32, H/8, 128),256>>>(cv_w + blk*128*9, cv_b + blk*128, H, W);
    else
      k_dwconv_tr<<<gs(128*L,BS),BS>>>(cv_w + blk*128*9, cv_b + blk*128, H, W);
    k_xproj_v  <<<dim3(gs(L,256),4,6),256>>>(xp_w + blk*4*36*128, L);
    k_delta_v  <<<dim3(gs(L,256),512),256>>>(dt_w + blk*4*128*4, dt_b + blk*4*128, L);
    k_scan     <<<dim3(64,4),512>>>(A_log + blk*4*128*16, L, H, W);
    k_post     <<<L/32,256>>>(Dp + blk*4*128, on_g + blk*128, on_b + blk*128, L);
    k_outproj_v<<<dim3(gs(L,256),16),256>>>(out_pw + blk*128*64, L, skipid);
  };

  const int skipid[3] = {4, 5, 6};
  int H = 64;
  for(int st=0; st<4; st++){
    vss(st*2,   H, -1);
    vss(st*2+1, H, (st < 3) ? skipid[st] : -1);
    if(st < 3){
      int Ho = H/2;
      dim3 gdn(gs(Ho,16), gs(Ho,8), 8);
      k_conv3x3_s2<<<gdn,256>>>(0, dn_w + st*64*64*9, dn_b + st*64, 3, H, H, Ho, Ho);
      k_ln2d_w<<<gs(Ho*Ho*32,BS),BS>>>(3, 0, dn_g + st*64, dn_lb + st*64, Ho*Ho);
      H = Ho;
    }
  }

  int cur = 0;
  for(int i=0;i<3;i++){
    int Ho = H*2;
    int oth = (cur == 0) ? 2 : 0;
    if(Ho % 32 == 0){
      dim3 gconv(Ho/32, Ho/2);
      k_conv3x3_tc<<<gconv,256>>>(cur, i*36864, up_b + i*64,
                                  skipid[2-i], oth, nullptr, H, H, Ho, Ho, 1);
    } else {
      dim3 gconv(gs(Ho,32), gs(Ho,8), 4);
      k_conv3x3_rt<<<gconv,256>>>(cur, up_w + i*64*64*9, up_b + i*64,
                                  skipid[2-i], oth, nullptr, H, H, Ho, Ho, 1);
    }
    cur = oth;
    H = Ho;
  }

  dim3 gfin(8, 128);
  k_conv3x3_tc<<<gfin,256>>>(cur, 3*36864, oc_b, -1, -1, (float*)d_out,
                             64, 64, 256, 256, 1);
}